// round 7
// baseline (speedup 1.0000x reference)
#include <cuda_runtime.h>
#include <cuda_bf16.h>
#include <cstdint>
#include <cstddef>

#define BB   256
#define LL   512
#define EE   256
#define HH   128
#define G4   512
#define TB   8
#define MROWS 131072          // L*B rows per cell
#define KTOT  768             // 3 * 256 (hi|hi|lo split-K)
#define NCH   24              // 768 / 32

// ---------------------------------------------------------------------------
// Device scratch
// ---------------------------------------------------------------------------
__device__ float g_gx[(size_t)2 * LL * BB * G4];            // 512 MB gates
__device__ __nv_bfloat16 g_ap[(size_t)2 * MROWS * KTOT];    // 402 MB A' (hi|hi|lo)
__device__ __nv_bfloat16 g_wp[(size_t)2 * G4 * KTOT];       // 1.5 MB W' (hi|lo|hi)
__device__ float g_h[(size_t)2 * BB * LL * HH];             // 128 MB hidden states

// ---------------------------------------------------------------------------
// Helpers
// ---------------------------------------------------------------------------
static __device__ __forceinline__ unsigned long long pack2(float x, float y) {
    unsigned long long r;
    asm("mov.b64 %0, {%1, %2};" : "=l"(r) : "f"(x), "f"(y));
    return r;
}
static __device__ __forceinline__ void fma2(unsigned long long& d,
                                            unsigned long long a,
                                            unsigned long long b) {
    asm("fma.rn.f32x2 %0, %1, %2, %0;" : "+l"(d) : "l"(a), "l"(b));
}
static __device__ __forceinline__ float2 unpack2(unsigned long long v) {
    float2 f;
    asm("mov.b64 {%0, %1}, %2;" : "=f"(f.x), "=f"(f.y) : "l"(v));
    return f;
}
static __device__ __forceinline__ uint32_t smem_u32(const void* p) {
    uint32_t a;
    asm("{ .reg .u64 t; cvta.to.shared.u64 t, %1; cvt.u32.u64 %0, t; }"
        : "=r"(a) : "l"(p));
    return a;
}
// st.async: remote smem store + remote mbarrier complete_tx (4 bytes)
static __device__ __forceinline__ void st_async_f32(uint32_t laddr, uint32_t lmbar,
                                                    uint32_t peer, float v) {
    asm volatile(
        "{ .reg .b32 ra, rm;\n\t"
        "mapa.shared::cluster.u32 ra, %0, %2;\n\t"
        "mapa.shared::cluster.u32 rm, %1, %2;\n\t"
        "st.async.shared::cluster.mbarrier::complete_tx::bytes.f32 [ra], %3, [rm]; }"
        :: "r"(laddr), "r"(lmbar), "r"(peer), "f"(v) : "memory");
}
// fast activations (ex2/rcp approx)
static __device__ __forceinline__ float sigm(float x) {
    float t;
    asm("mul.f32 %0, %1, 0fBFB8AA3B;" : "=f"(t) : "f"(x));   // -x*log2(e)
    asm("ex2.approx.f32 %0, %0;" : "+f"(t));
    float r = t + 1.0f;
    asm("rcp.approx.f32 %0, %0;" : "+f"(r));
    return r;
}
static __device__ __forceinline__ float tanha(float x) {
    x = fminf(fmaxf(x, -9.0f), 9.0f);
    float t;
    asm("mul.f32 %0, %1, 0f4038AA3B;" : "=f"(t) : "f"(x));   // 2x*log2(e)
    asm("ex2.approx.f32 %0, %0;" : "+f"(t));                  // e^{2x}
    float den = t + 1.0f;
    asm("rcp.approx.f32 %0, %0;" : "+f"(den));
    return (t - 1.0f) * den;
}
// cp.async
static __device__ __forceinline__ void cp16(uint32_t dst, const void* src) {
    asm volatile("cp.async.cg.shared.global [%0], [%1], 16;"
                 :: "r"(dst), "l"(src) : "memory");
}
static __device__ __forceinline__ void cp_commit() {
    asm volatile("cp.async.commit_group;" ::: "memory");
}
template <int N>
static __device__ __forceinline__ void cp_wait() {
    asm volatile("cp.async.wait_group %0;" :: "n"(N) : "memory");
}
// ldmatrix x4 (b16)
static __device__ __forceinline__ void ldx4(uint32_t* r, uint32_t addr) {
    asm volatile("ldmatrix.sync.aligned.m8n8.x4.shared.b16 {%0,%1,%2,%3}, [%4];"
                 : "=r"(r[0]), "=r"(r[1]), "=r"(r[2]), "=r"(r[3]) : "r"(addr));
}
// bf16 HMMA m16n8k16, fp32 accum
static __device__ __forceinline__ void mma16816(float* c, const uint32_t* a,
                                                uint32_t b0, uint32_t b1) {
    asm volatile(
        "mma.sync.aligned.m16n8k16.row.col.f32.bf16.bf16.f32 "
        "{%0,%1,%2,%3}, {%4,%5,%6,%7}, {%8,%9}, {%0,%1,%2,%3};"
        : "+f"(c[0]), "+f"(c[1]), "+f"(c[2]), "+f"(c[3])
        : "r"(a[0]), "r"(a[1]), "r"(a[2]), "r"(a[3]), "r"(b0), "r"(b1));
}
static __device__ __forceinline__ uint32_t bfpack(__nv_bfloat16 a, __nv_bfloat16 b) {
    return (uint32_t)__bfloat16_as_ushort(a) | ((uint32_t)__bfloat16_as_ushort(b) << 16);
}
// mbarrier ops
#define MBAR_INIT(a, c) \
    asm volatile("mbarrier.init.shared.b64 [%0], %1;" :: "r"(a), "r"((uint32_t)(c)) : "memory")
#define MBAR_EXPECT(a, tx) \
    asm volatile("mbarrier.arrive.expect_tx.shared.b64 _, [%0], %1;" \
                 :: "r"(a), "r"((uint32_t)(tx)) : "memory")
#define MBAR_WAIT(a, ph) do {                                                        \
    uint32_t _m = (a); uint32_t _p = (ph); uint32_t _d;                              \
    asm volatile("{ .reg .pred p; mbarrier.try_wait.parity.acquire.cta.shared::cta.b64 p, [%1], %2;" \
                 " selp.b32 %0,1,0,p; }" : "=r"(_d) : "r"(_m), "r"(_p) : "memory");  \
    if (!_d) {                                                                       \
        asm volatile("{ .reg .pred P1; WL%=: mbarrier.try_wait.parity.acquire.cta.shared::cta.b64 P1, [%0], %1, 0x989680;" \
                     " @P1 bra.uni WD%=; bra.uni WL%=; WD%=: }"                      \
                     :: "r"(_m), "r"(_p) : "memory");                                \
    } } while (0)

// ---------------------------------------------------------------------------
// Convert X -> A' = [hi | hi | lo]  (bf16, row r = t*256+b, K'=768)
// ---------------------------------------------------------------------------
__global__ __launch_bounds__(256) void k_convert(const float* __restrict__ Xh,
                                                 const float* __restrict__ Xf) {
    size_t i = (size_t)blockIdx.x * 256 + threadIdx.x;
    int e8 = (int)(i & 31);
    size_t rr = i >> 5;                                  // cell*MROWS + r
    int cell = (int)(rr >> 17);
    int r = (int)(rr & (MROWS - 1));
    int t = r >> 8, b = r & 255;
    const float* X = cell ? Xf : Xh;
    const float4* src = reinterpret_cast<const float4*>(X + ((size_t)b * LL + t) * EE + e8 * 8);
    float4 v0 = src[0], v1 = src[1];
    float x[8] = {v0.x, v0.y, v0.z, v0.w, v1.x, v1.y, v1.z, v1.w};
    __nv_bfloat16 hi[8], lo[8];
#pragma unroll
    for (int j = 0; j < 8; j++) {
        hi[j] = __float2bfloat16(x[j]);
        lo[j] = __float2bfloat16(x[j] - __bfloat162float(hi[j]));
    }
    uint4 ph, pl;
    ph.x = bfpack(hi[0], hi[1]); ph.y = bfpack(hi[2], hi[3]);
    ph.z = bfpack(hi[4], hi[5]); ph.w = bfpack(hi[6], hi[7]);
    pl.x = bfpack(lo[0], lo[1]); pl.y = bfpack(lo[2], lo[3]);
    pl.z = bfpack(lo[4], lo[5]); pl.w = bfpack(lo[6], lo[7]);
    __nv_bfloat16* dst = g_ap + rr * KTOT + e8 * 8;
    *reinterpret_cast<uint4*>(dst)       = ph;
    *reinterpret_cast<uint4*>(dst + 256) = ph;
    *reinterpret_cast<uint4*>(dst + 512) = pl;
}

// W' = [hi | lo | hi]
__global__ __launch_bounds__(256) void k_convert_w(const float* __restrict__ Wh,
                                                   const float* __restrict__ Wf) {
    int i = blockIdx.x * 256 + threadIdx.x;
    int e8 = i & 31;
    int nn = i >> 5;                                     // cell*512 + n
    int cell = nn >> 9;
    int n = nn & 511;
    const float* W = cell ? Wf : Wh;
    const float4* src = reinterpret_cast<const float4*>(W + (size_t)n * EE + e8 * 8);
    float4 v0 = src[0], v1 = src[1];
    float x[8] = {v0.x, v0.y, v0.z, v0.w, v1.x, v1.y, v1.z, v1.w};
    __nv_bfloat16 hi[8], lo[8];
#pragma unroll
    for (int j = 0; j < 8; j++) {
        hi[j] = __float2bfloat16(x[j]);
        lo[j] = __float2bfloat16(x[j] - __bfloat162float(hi[j]));
    }
    uint4 ph, pl;
    ph.x = bfpack(hi[0], hi[1]); ph.y = bfpack(hi[2], hi[3]);
    ph.z = bfpack(hi[4], hi[5]); ph.w = bfpack(hi[6], hi[7]);
    pl.x = bfpack(lo[0], lo[1]); pl.y = bfpack(lo[2], lo[3]);
    pl.z = bfpack(lo[4], lo[5]); pl.w = bfpack(lo[6], lo[7]);
    __nv_bfloat16* dst = g_wp + (size_t)nn * KTOT + e8 * 8;
    *reinterpret_cast<uint4*>(dst)       = ph;
    *reinterpret_cast<uint4*>(dst + 256) = pl;   // pairs with A hi
    *reinterpret_cast<uint4*>(dst + 512) = ph;   // pairs with A lo
}

// ---------------------------------------------------------------------------
// Phase 1 GEMM via mma.sync bf16 (unchanged — validated R4-R6)
// ---------------------------------------------------------------------------
#define ASTRIDE 40

__global__ __launch_bounds__(256, 2) void k_mma_gemm(
    const float* __restrict__ bih_h, const float* __restrict__ bhh_h,
    const float* __restrict__ bih_f, const float* __restrict__ bhh_f)
{
    __shared__ __align__(16) __nv_bfloat16 As[2][128 * ASTRIDE];
    __shared__ __align__(16) __nv_bfloat16 Bs[2][128 * ASTRIDE];
    __shared__ float bias_s[128];

    const int tid  = threadIdx.x;
    const int wid  = tid >> 5;
    const int lane = tid & 31;
    const int n0 = blockIdx.x * 128;
    const int m0 = blockIdx.y * 128;
    const int cell = m0 >> 17;

    if (tid < 128) {
        const float* bi = cell ? bih_f : bih_h;
        const float* bh = cell ? bhh_f : bhh_h;
        bias_s[tid] = bi[n0 + tid] + bh[n0 + tid];
    }

    const __nv_bfloat16* Asrc = g_ap + (size_t)m0 * KTOT;
    const __nv_bfloat16* Bsrc = g_wp + ((size_t)cell * G4 + n0) * KTOT;

    const uint32_t sa = smem_u32(&As[0][0]);
    const uint32_t sb = smem_u32(&Bs[0][0]);
    const uint32_t bufstride = 128 * ASTRIDE * 2;

    const int lrow = tid >> 1;
    const int lu   = (tid & 1) * 2;
    const uint32_t a_dst0 = sa + lrow * (ASTRIDE * 2) + lu * 16;
    const uint32_t b_dst0 = sb + lrow * (ASTRIDE * 2) + lu * 16;
    const __nv_bfloat16* a_src0 = Asrc + (size_t)lrow * KTOT + lu * 8;
    const __nv_bfloat16* b_src0 = Bsrc + (size_t)lrow * KTOT + lu * 8;

#define LOAD_CHUNK(c)                                                      \
    do {                                                                   \
        int _buf = (c) & 1;                                                \
        int _k0 = (c) * 32;                                                \
        cp16(a_dst0 + _buf * bufstride,      a_src0 + _k0);                \
        cp16(a_dst0 + _buf * bufstride + 16, a_src0 + _k0 + 8);            \
        cp16(b_dst0 + _buf * bufstride,      b_src0 + _k0);                \
        cp16(b_dst0 + _buf * bufstride + 16, b_src0 + _k0 + 8);            \
        cp_commit();                                                       \
    } while (0)

    const int warp_m = wid & 3;
    const int warp_n = wid >> 2;

    uint32_t a_addr[2];
#pragma unroll
    for (int im = 0; im < 2; im++) {
        int row = warp_m * 32 + im * 16 + (lane & 15);
        a_addr[im] = sa + row * (ASTRIDE * 2) + (lane >> 4) * 16;
    }
    uint32_t b_addr[4];
#pragma unroll
    for (int ip = 0; ip < 4; ip++) {
        int row = warp_n * 64 + ip * 16 + (lane >> 4) * 8 + (lane & 7);
        b_addr[ip] = sb + row * (ASTRIDE * 2) + ((lane >> 3) & 1) * 16;
    }

    float acc[2][8][4];
#pragma unroll
    for (int im = 0; im < 2; im++)
#pragma unroll
        for (int in = 0; in < 8; in++)
#pragma unroll
            for (int q = 0; q < 4; q++) acc[im][in][q] = 0.0f;

    LOAD_CHUNK(0);

    for (int c = 0; c < NCH; ++c) {
        if (c + 1 < NCH) { LOAD_CHUNK(c + 1); cp_wait<1>(); }
        else             { cp_wait<0>(); }
        __syncthreads();

        const uint32_t boff = (uint32_t)(c & 1) * bufstride;
#pragma unroll
        for (int ks = 0; ks < 2; ks++) {
            const uint32_t kb = boff + ks * 32;
            uint32_t afr[2][4];
            ldx4(afr[0], a_addr[0] + kb);
            ldx4(afr[1], a_addr[1] + kb);
            uint32_t bfr[16];
            ldx4(bfr + 0,  b_addr[0] + kb);
            ldx4(bfr + 4,  b_addr[1] + kb);
            ldx4(bfr + 8,  b_addr[2] + kb);
            ldx4(bfr + 12, b_addr[3] + kb);
#pragma unroll
            for (int im = 0; im < 2; im++)
#pragma unroll
                for (int in = 0; in < 8; in++)
                    mma16816(acc[im][in], afr[im], bfr[in * 2], bfr[in * 2 + 1]);
        }
        __syncthreads();
    }

#pragma unroll
    for (int im = 0; im < 2; im++) {
#pragma unroll
        for (int h = 0; h < 2; h++) {
            int m = m0 + warp_m * 32 + im * 16 + h * 8 + (lane >> 2);
            int r = m & (MROWS - 1);
            int t = r >> 8, b = r & 255;
            float* gp = g_gx + (((size_t)cell * LL + t) * BB + b) * G4 + n0;
#pragma unroll
            for (int in = 0; in < 8; in++) {
                int col = warp_n * 64 + in * 8 + (lane & 3) * 2;
                float2 v;
                v.x = acc[im][in][2 * h + 0] + bias_s[col];
                v.y = acc[im][in][2 * h + 1] + bias_s[col + 1];
                *reinterpret_cast<float2*>(gp + col) = v;
            }
        }
    }
}

// ---------------------------------------------------------------------------
// Phase 2: recurrent LSTM. Cluster of 4 CTAs per batch-tile; each CTA runs
// BOTH cells (independent chains) interleaved so DSMEM/sync latency of one
// cell hides under the other's matvec. h exchange via st.async + mbarrier
// (no barrier.cluster in the loop, no L1 flush).
// ---------------------------------------------------------------------------
#define HPAD 136
static __device__ __forceinline__ int hidx(int j) { return j + ((j >> 6) << 2); }

__global__ __launch_bounds__(256, 1) __cluster_dims__(4, 1, 1)
void k_recurrent(const float* __restrict__ Whh_h,
                 const float* __restrict__ Whh_f)
{
    __shared__ float hs_h[2][TB][HPAD];
    __shared__ float hs_f[2][TB][HPAD];
    __shared__ float gh[128][TB + 1];
    __shared__ float gf[128][TB + 1];
    __shared__ __align__(8) uint64_t mbar[2];   // full_h, full_f

    const int tid = threadIdx.x;
    uint32_t rank;
    asm("mov.u32 %0, %%cluster_ctarank;" : "=r"(rank));
    const int q  = blockIdx.x >> 2;        // batch tile 0..31
    const int b0 = q * TB;

    // matvec mapping: 128 local gate rows x 2 halves
    const int row  = tid >> 1;
    const int half = tid & 1;
    const int g    = row >> 5;
    const int ju   = row & 31;
    const int n    = g * HH + (int)rank * 32 + ju;

    unsigned long long w2h[32], w2f[32];
    {
        const float2* wr = reinterpret_cast<const float2*>(Whh_h + (size_t)n * HH + half * 64);
        const float2* wf_ = reinterpret_cast<const float2*>(Whh_f + (size_t)n * HH + half * 64);
#pragma unroll
        for (int i = 0; i < 32; i++) {
            float2 a = wr[i]; w2h[i] = pack2(a.x, a.y);
            float2 b = wf_[i]; w2f[i] = pack2(b.x, b.y);
        }
    }

    // pointwise mapping
    const int pb = tid >> 5;
    const int pj = tid & 31;
    const int jglob = (int)rank * 32 + pj;
    const uint32_t ah[2] = { smem_u32(&hs_h[0][pb][hidx(jglob)]),
                             smem_u32(&hs_h[1][pb][hidx(jglob)]) };
    const uint32_t af[2] = { smem_u32(&hs_f[0][pb][hidx(jglob)]),
                             smem_u32(&hs_f[1][pb][hidx(jglob)]) };
    const uint32_t mb_h = smem_u32(&mbar[0]);
    const uint32_t mb_f = smem_u32(&mbar[1]);
    float* hg_h = g_h + (((size_t)0 * BB + b0 + pb) * LL) * HH + jglob;
    float* hg_f = g_h + (((size_t)1 * BB + b0 + pb) * LL) * HH + jglob;

    for (int i = tid; i < 2 * TB * HPAD; i += 256) {
        (&hs_h[0][0][0])[i] = 0.0f;
        (&hs_f[0][0][0])[i] = 0.0f;
    }
    float c_h = 0.0f, c_f = 0.0f;
    if (tid == 0) { MBAR_INIT(mb_h, 1); MBAR_INIT(mb_f, 1); }
    __syncthreads();
    asm volatile("barrier.cluster.arrive.aligned;" ::: "memory");
    asm volatile("barrier.cluster.wait.aligned;"   ::: "memory");
    if (tid == 0) { MBAR_EXPECT(mb_h, 3072); MBAR_EXPECT(mb_f, 3072); }

    // Gx pointers: 4 gate values per cell for (pb, pj)
    const float* gxb_h = g_gx + ((size_t)0 * LL * BB + (b0 + pb)) * G4 + jglob;
    const float* gxb_f = g_gx + ((size_t)1 * LL * BB + (b0 + pb)) * G4 + jglob;
    float grh[4], grf[4];
#pragma unroll
    for (int gi = 0; gi < 4; gi++) {
        grh[gi] = gxb_h[gi * HH];
        grf[gi] = gxb_f[gi * HH];
    }

    int buf = 0;
    uint32_t par = 0;
    for (int t = 0; t < LL; t++) {
        const int nb = buf ^ 1;

        // ======== cell h: matvec ========
#pragma unroll
        for (int bp = 0; bp < TB; bp += 2) {
            const longlong2* hp0 =
                reinterpret_cast<const longlong2*>(&hs_h[buf][bp][half * 68]);
            const longlong2* hp1 =
                reinterpret_cast<const longlong2*>(&hs_h[buf][bp + 1][half * 68]);
            unsigned long long a00 = 0ull, a01 = 0ull, a10 = 0ull, a11 = 0ull;
#pragma unroll
            for (int i = 0; i < 16; i++) {
                longlong2 v0 = hp0[i];
                longlong2 v1 = hp1[i];
                fma2(a00, (unsigned long long)v0.x, w2h[2 * i]);
                fma2(a01, (unsigned long long)v0.y, w2h[2 * i + 1]);
                fma2(a10, (unsigned long long)v1.x, w2h[2 * i]);
                fma2(a11, (unsigned long long)v1.y, w2h[2 * i + 1]);
            }
            float2 s00 = unpack2(a00), s01 = unpack2(a01);
            float2 s10 = unpack2(a10), s11 = unpack2(a11);
            float p0 = (s00.x + s00.y) + (s01.x + s01.y);
            float p1 = (s10.x + s10.y) + (s11.x + s11.y);
            float t0 = p0 + __shfl_xor_sync(0xffffffffu, p0, 1);
            float t1 = p1 + __shfl_xor_sync(0xffffffffu, p1, 1);
            if (!half) {
                gh[row][bp]     = t0;
                gh[row][bp + 1] = t1;
            }
        }
        __syncthreads();

        // ======== cell h: pointwise + async broadcast ========
        {
            float gi_ = gh[pj][pb]        + grh[0];
            float gf_ = gh[32 + pj][pb]   + grh[1];
            float gg_ = gh[64 + pj][pb]   + grh[2];
            float go_ = gh[96 + pj][pb]   + grh[3];
            float ig = sigm(gi_), fg = sigm(gf_);
            float gv = tanha(gg_), og = sigm(go_);
            c_h = fg * c_h + ig * gv;
            float hv = og * tanha(c_h);
            hs_h[nb][pb][hidx(jglob)] = hv;
#pragma unroll
            for (int r = 1; r < 4; r++)
                st_async_f32(ah[nb], mb_h, (rank + r) & 3u, hv);
            hg_h[(size_t)t * HH] = hv;
        }

        // ======== cell f: matvec (covers h's DSMEM latency) ========
#pragma unroll
        for (int bp = 0; bp < TB; bp += 2) {
            const longlong2* hp0 =
                reinterpret_cast<const longlong2*>(&hs_f[buf][bp][half * 68]);
            const longlong2* hp1 =
                reinterpret_cast<const longlong2*>(&hs_f[buf][bp + 1][half * 68]);
            unsigned long long a00 = 0ull, a01 = 0ull, a10 = 0ull, a11 = 0ull;
#pragma unroll
            for (int i = 0; i < 16; i++) {
                longlong2 v0 = hp0[i];
                longlong2 v1 = hp1[i];
                fma2(a00, (unsigned long long)v0.x, w2f[2 * i]);
                fma2(a01, (unsigned long long)v0.y, w2f[2 * i + 1]);
                fma2(a10, (unsigned long long)v1.x, w2f[2 * i]);
                fma2(a11, (unsigned long long)v1.y, w2f[2 * i + 1]);
            }
            float2 s00 = unpack2(a00), s01 = unpack2(a01);
            float2 s10 = unpack2(a10), s11 = unpack2(a11);
            float p0 = (s00.x + s00.y) + (s01.x + s01.y);
            float p1 = (s10.x + s10.y) + (s11.x + s11.y);
            float t0 = p0 + __shfl_xor_sync(0xffffffffu, p0, 1);
            float t1 = p1 + __shfl_xor_sync(0xffffffffu, p1, 1);
            if (!half) {
                gf[row][bp]     = t0;
                gf[row][bp + 1] = t1;
            }
        }
        __syncthreads();

        // ======== cell f: pointwise + async broadcast ========
        {
            float gi_ = gf[pj][pb]        + grf[0];
            float gf_ = gf[32 + pj][pb]   + grf[1];
            float gg_ = gf[64 + pj][pb]   + grf[2];
            float go_ = gf[96 + pj][pb]   + grf[3];
            float ig = sigm(gi_), fg2 = sigm(gf_);
            float gv = tanha(gg_), og = sigm(go_);
            c_f = fg2 * c_f + ig * gv;
            float hv = og * tanha(c_f);
            hs_f[nb][pb][hidx(jglob)] = hv;
#pragma unroll
            for (int r = 1; r < 4; r++)
                st_async_f32(af[nb], mb_f, (rank + r) & 3u, hv);
            hg_f[(size_t)t * HH] = hv;
        }

        // prefetch Gx for t+1
        if (t + 1 < LL) {
            const float* gp_h = gxb_h + (size_t)(t + 1) * BB * G4;
            const float* gp_f = gxb_f + (size_t)(t + 1) * BB * G4;
#pragma unroll
            for (int gi2 = 0; gi2 < 4; gi2++) {
                grh[gi2] = gp_h[gi2 * HH];
                grf[gi2] = gp_f[gi2 * HH];
            }
        }

        // ======== wait for peers' h(t) stores, arm next phase ========
        MBAR_WAIT(mb_h, par);
        MBAR_WAIT(mb_f, par);
        if (tid == 0) { MBAR_EXPECT(mb_h, 3072); MBAR_EXPECT(mb_f, 3072); }
        __syncthreads();
        par ^= 1;
        buf = nb;
    }

    asm volatile("barrier.cluster.arrive.aligned;" ::: "memory");
    asm volatile("barrier.cluster.wait.aligned;"   ::: "memory");
}

// ---------------------------------------------------------------------------
// Phase 3: y[b][t] = W_ffn . [h_h(b,t); h_f(b,t)] + b_ffn
// ---------------------------------------------------------------------------
__global__ __launch_bounds__(256) void k_finalize(float* __restrict__ out,
                                                  const float* __restrict__ Wffn,
                                                  const float* __restrict__ bffn) {
    __shared__ float wf[2 * HH];
    const int b = blockIdx.x;
    const int tid = threadIdx.x;
    wf[tid] = Wffn[tid];
    __syncthreads();
    const float bias = bffn[0];

    for (int t = tid; t < LL; t += 256) {
        const float4* p0 = reinterpret_cast<const float4*>(
            g_h + (((size_t)0 * BB + b) * LL + t) * HH);
        const float4* p1 = reinterpret_cast<const float4*>(
            g_h + (((size_t)1 * BB + b) * LL + t) * HH);
        float acc = bias;
#pragma unroll 8
        for (int q = 0; q < 32; q++) {
            float4 a = p0[q];
            acc += a.x * wf[4 * q] + a.y * wf[4 * q + 1]
                 + a.z * wf[4 * q + 2] + a.w * wf[4 * q + 3];
        }
#pragma unroll 8
        for (int q = 0; q < 32; q++) {
            float4 a = p1[q];
            acc += a.x * wf[128 + 4 * q] + a.y * wf[128 + 4 * q + 1]
                 + a.z * wf[128 + 4 * q + 2] + a.w * wf[128 + 4 * q + 3];
        }
        out[(size_t)b * LL + t] = acc;
    }
}

// ---------------------------------------------------------------------------
extern "C" void kernel_launch(void* const* d_in, const int* in_sizes, int n_in,
                              void* d_out, int out_size) {
    const float* hist  = (const float*)d_in[0];
    const float* fut   = (const float*)d_in[1];
    const float* Wih_h = (const float*)d_in[2];
    const float* Whh_h = (const float*)d_in[3];
    const float* bih_h = (const float*)d_in[4];
    const float* bhh_h = (const float*)d_in[5];
    const float* Wih_f = (const float*)d_in[6];
    const float* Whh_f = (const float*)d_in[7];
    const float* bih_f = (const float*)d_in[8];
    const float* bhh_f = (const float*)d_in[9];
    const float* Wffn  = (const float*)d_in[10];
    const float* bffn  = (const float*)d_in[11];
    float* out = (float*)d_out;

    k_convert<<<(2 * MROWS * 32) / 256, 256>>>(hist, fut);
    k_convert_w<<<(2 * G4 * 32) / 256, 256>>>(Wih_h, Wih_f);

    dim3 gg(G4 / 128, (2 * MROWS) / 128);   // (4, 2048)
    k_mma_gemm<<<gg, 256>>>(bih_h, bhh_h, bih_f, bhh_f);

    k_recurrent<<<128, 256>>>(Whh_h, Whh_f);

    k_finalize<<<BB, 256>>>(out, Wffn, bffn);
}

// round 8
// speedup vs baseline: 1.1255x; 1.1255x over previous
#include <cuda_runtime.h>
#include <cuda_bf16.h>
#include <cstdint>
#include <cstddef>

#define BB   256
#define LL   512
#define EE   256
#define HH   128
#define G4   512
#define TB   8
#define MROWS 131072          // L*B rows per cell
#define WKT  512              // W' width: [hi(256) | lo(256)]

// ---------------------------------------------------------------------------
// Device scratch
// ---------------------------------------------------------------------------
__device__ float g_gx[(size_t)2 * LL * BB * G4];            // 512 MB gates
__device__ __nv_bfloat16 g_wp[(size_t)2 * G4 * WKT];        // 1 MB W' (hi|lo)
__device__ float g_h[(size_t)2 * BB * LL * HH];             // 128 MB hidden states

// ---------------------------------------------------------------------------
// Helpers
// ---------------------------------------------------------------------------
static __device__ __forceinline__ unsigned long long pack2(float x, float y) {
    unsigned long long r;
    asm("mov.b64 %0, {%1, %2};" : "=l"(r) : "f"(x), "f"(y));
    return r;
}
static __device__ __forceinline__ void fma2(unsigned long long& d,
                                            unsigned long long a,
                                            unsigned long long b) {
    asm("fma.rn.f32x2 %0, %1, %2, %0;" : "+l"(d) : "l"(a), "l"(b));
}
static __device__ __forceinline__ float2 unpack2(unsigned long long v) {
    float2 f;
    asm("mov.b64 {%0, %1}, %2;" : "=f"(f.x), "=f"(f.y) : "l"(v));
    return f;
}
static __device__ __forceinline__ uint32_t smem_u32(const void* p) {
    uint32_t a;
    asm("{ .reg .u64 t; cvta.to.shared.u64 t, %1; cvt.u32.u64 %0, t; }"
        : "=r"(a) : "l"(p));
    return a;
}
static __device__ __forceinline__ void st_remote_f32(uint32_t laddr, uint32_t peer, float v) {
    asm volatile(
        "{ .reg .b32 ra; mapa.shared::cluster.u32 ra, %0, %1; "
        "st.shared::cluster.f32 [ra], %2; }"
        :: "r"(laddr), "r"(peer), "f"(v) : "memory");
}
// fast activations (ex2/rcp approx)
static __device__ __forceinline__ float sigm(float x) {
    float t;
    asm("mul.f32 %0, %1, 0fBFB8AA3B;" : "=f"(t) : "f"(x));   // -x*log2(e)
    asm("ex2.approx.f32 %0, %0;" : "+f"(t));
    float r = t + 1.0f;
    asm("rcp.approx.f32 %0, %0;" : "+f"(r));
    return r;
}
static __device__ __forceinline__ float tanha(float x) {
    x = fminf(fmaxf(x, -9.0f), 9.0f);
    float t;
    asm("mul.f32 %0, %1, 0f4038AA3B;" : "=f"(t) : "f"(x));   // 2x*log2(e)
    asm("ex2.approx.f32 %0, %0;" : "+f"(t));                  // e^{2x}
    float den = t + 1.0f;
    asm("rcp.approx.f32 %0, %0;" : "+f"(den));
    return (t - 1.0f) * den;
}
// cp.async
static __device__ __forceinline__ void cp16(uint32_t dst, const void* src) {
    asm volatile("cp.async.cg.shared.global [%0], [%1], 16;"
                 :: "r"(dst), "l"(src) : "memory");
}
static __device__ __forceinline__ void cp_commit() {
    asm volatile("cp.async.commit_group;" ::: "memory");
}
template <int N>
static __device__ __forceinline__ void cp_wait() {
    asm volatile("cp.async.wait_group %0;" :: "n"(N) : "memory");
}
// ldmatrix x4 (b16)
static __device__ __forceinline__ void ldx4(uint32_t* r, uint32_t addr) {
    asm volatile("ldmatrix.sync.aligned.m8n8.x4.shared.b16 {%0,%1,%2,%3}, [%4];"
                 : "=r"(r[0]), "=r"(r[1]), "=r"(r[2]), "=r"(r[3]) : "r"(addr));
}
// bf16 HMMA m16n8k16, fp32 accum
static __device__ __forceinline__ void mma16816(float* c, const uint32_t* a,
                                                uint32_t b0, uint32_t b1) {
    asm volatile(
        "mma.sync.aligned.m16n8k16.row.col.f32.bf16.bf16.f32 "
        "{%0,%1,%2,%3}, {%4,%5,%6,%7}, {%8,%9}, {%0,%1,%2,%3};"
        : "+f"(c[0]), "+f"(c[1]), "+f"(c[2]), "+f"(c[3])
        : "r"(a[0]), "r"(a[1]), "r"(a[2]), "r"(a[3]), "r"(b0), "r"(b1));
}
static __device__ __forceinline__ uint32_t bfpack(__nv_bfloat16 a, __nv_bfloat16 b) {
    return (uint32_t)__bfloat16_as_ushort(a) | ((uint32_t)__bfloat16_as_ushort(b) << 16);
}

// ---------------------------------------------------------------------------
// W' = [hi | lo]  (512 bf16 per row)
// ---------------------------------------------------------------------------
__global__ __launch_bounds__(256) void k_convert_w(const float* __restrict__ Wh,
                                                   const float* __restrict__ Wf) {
    int i = blockIdx.x * 256 + threadIdx.x;               // 2*512*32 total
    int e8 = i & 31;
    int nn = i >> 5;                                      // cell*512 + n
    int cell = nn >> 9;
    int n = nn & 511;
    const float* W = cell ? Wf : Wh;
    const float4* src = reinterpret_cast<const float4*>(W + (size_t)n * EE + e8 * 8);
    float4 v0 = src[0], v1 = src[1];
    float x[8] = {v0.x, v0.y, v0.z, v0.w, v1.x, v1.y, v1.z, v1.w};
    __nv_bfloat16 hi[8], lo[8];
#pragma unroll
    for (int j = 0; j < 8; j++) {
        hi[j] = __float2bfloat16(x[j]);
        lo[j] = __float2bfloat16(x[j] - __bfloat162float(hi[j]));
    }
    uint4 ph, pl;
    ph.x = bfpack(hi[0], hi[1]); ph.y = bfpack(hi[2], hi[3]);
    ph.z = bfpack(hi[4], hi[5]); ph.w = bfpack(hi[6], hi[7]);
    pl.x = bfpack(lo[0], lo[1]); pl.y = bfpack(lo[2], lo[3]);
    pl.z = bfpack(lo[4], lo[5]); pl.w = bfpack(lo[6], lo[7]);
    __nv_bfloat16* dst = g_wp + (size_t)nn * WKT + e8 * 8;
    *reinterpret_cast<uint4*>(dst)       = ph;
    *reinterpret_cast<uint4*>(dst + 256) = pl;
}

// ---------------------------------------------------------------------------
// Phase 1 fused GEMM: Gx = X @ W^T + bias with in-kernel hi/lo split.
// CTA 128x128, 512 threads (16 warps, warp tile 32x32), K-chunks of 32 fp32.
// Per chunk: 3 sub-products  Xhi*Whi + Xhi*Wlo + Xlo*Whi  (fp32 accum).
// X staged via LDG->regs->convert->STS; W' via cp.async. 1 sync per chunk.
// smem byte layout (stride 40 bf16 = 80 B per row, validated in R4):
//   [0      ,20480) Ah[2]   [20480,40960) Al[2]
//   [40960  ,61440) Bh[2]   [61440,81920) Bl[2]   [81920,82432) bias(f32)
// ---------------------------------------------------------------------------
#define ABUF 10240                    // bytes per 128x40-bf16 buffer
#define OFF_AH 0
#define OFF_AL 20480
#define OFF_BH 40960
#define OFF_BL 61440
#define OFF_BIAS 81920
#define SMEM_P1 (81920 + 512)

__global__ __launch_bounds__(512, 1) void k_mma_gemm(
    const float* __restrict__ Xh, const float* __restrict__ Xf,
    const float* __restrict__ bih_h, const float* __restrict__ bhh_h,
    const float* __restrict__ bih_f, const float* __restrict__ bhh_f)
{
    extern __shared__ __align__(16) char smem[];
    const uint32_t sbase = smem_u32(smem);
    float* bias_s = reinterpret_cast<float*>(smem + OFF_BIAS);

    const int tid  = threadIdx.x;
    const int wid  = tid >> 5;
    const int lane = tid & 31;
    const int n0 = blockIdx.x * 128;
    const int m0 = blockIdx.y * 128;
    const int cell = m0 >> 17;

    if (tid < 128) {
        const float* bi = cell ? bih_f : bih_h;
        const float* bh = cell ? bhh_f : bhh_h;
        bias_s[tid] = bi[n0 + tid] + bh[n0 + tid];
    }

    const float* X = cell ? Xf : Xh;

    // ---- A loader mapping: row = tid>>2, quarter = (tid&3)*8 floats
    const int arow = tid >> 2;
    const int aq   = (tid & 3) * 8;
    const int mA = m0 + arow;
    const int rA = mA & (MROWS - 1);
    const float* xsrc = X + (((size_t)(rA & 255)) * LL + (rA >> 8)) * EE + aq;
    const uint32_t a_sts_h = sbase + OFF_AH + arow * 80 + aq * 2;
    const uint32_t a_sts_l = sbase + OFF_AL + arow * 80 + aq * 2;

    // ---- B loader mapping: 2 cp16 per thread
    const int btile = tid >> 8;               // 0 = hi, 1 = lo
    const int brr   = tid & 255;
    const int brow  = brr >> 1;
    const int bu    = (brr & 1) * 2;          // pieces bu, bu+1 (of 4 per row)
    const __nv_bfloat16* bsrc =
        g_wp + ((size_t)cell * G4 + n0 + brow) * WKT + btile * 256 + bu * 8;
    const uint32_t b_dst = sbase + (btile ? OFF_BL : OFF_BH) + brow * 80 + bu * 16;

    // ---- warp tiling 32x32: warp_m = wid&3, warp_n = wid>>2
    const int warp_m = wid & 3;
    const int warp_n = wid >> 2;
    uint32_t a_off[2];
#pragma unroll
    for (int im = 0; im < 2; im++)
        a_off[im] = (warp_m * 32 + im * 16 + (lane & 15)) * 80 + (lane >> 4) * 16;
    uint32_t b_off[2];
#pragma unroll
    for (int ip = 0; ip < 2; ip++)
        b_off[ip] = (warp_n * 32 + ip * 16 + (lane >> 4) * 8 + (lane & 7)) * 80
                  + ((lane >> 3) & 1) * 16;

    float acc[2][4][4];
#pragma unroll
    for (int im = 0; im < 2; im++)
#pragma unroll
        for (int in = 0; in < 4; in++)
#pragma unroll
            for (int q = 0; q < 4; q++) acc[im][in][q] = 0.0f;

    // ---- prologue: X chunk 0 into regs, B chunk 0 via cp.async
    float4 xr0 = reinterpret_cast<const float4*>(xsrc)[0];
    float4 xr1 = reinterpret_cast<const float4*>(xsrc)[1];
    cp16(b_dst,      bsrc);
    cp16(b_dst + 16, bsrc + 8);
    cp_commit();

    for (int k = 0; k < 8; ++k) {
        const uint32_t boff = (uint32_t)(k & 1) * ABUF;

        // convert current X regs -> STS hi/lo
        {
            float x8[8] = {xr0.x, xr0.y, xr0.z, xr0.w, xr1.x, xr1.y, xr1.z, xr1.w};
            __nv_bfloat16 hi[8], lo[8];
#pragma unroll
            for (int j = 0; j < 8; j++) {
                hi[j] = __float2bfloat16(x8[j]);
                lo[j] = __float2bfloat16(x8[j] - __bfloat162float(hi[j]));
            }
            uint4 ph, pl;
            ph.x = bfpack(hi[0], hi[1]); ph.y = bfpack(hi[2], hi[3]);
            ph.z = bfpack(hi[4], hi[5]); ph.w = bfpack(hi[6], hi[7]);
            pl.x = bfpack(lo[0], lo[1]); pl.y = bfpack(lo[2], lo[3]);
            pl.z = bfpack(lo[4], lo[5]); pl.w = bfpack(lo[6], lo[7]);
            asm volatile("st.shared.v4.b32 [%0], {%1,%2,%3,%4};"
                         :: "r"(a_sts_h + boff), "r"(ph.x), "r"(ph.y), "r"(ph.z), "r"(ph.w)
                         : "memory");
            asm volatile("st.shared.v4.b32 [%0], {%1,%2,%3,%4};"
                         :: "r"(a_sts_l + boff), "r"(pl.x), "r"(pl.y), "r"(pl.z), "r"(pl.w)
                         : "memory");
        }
        // prefetch next X chunk
        if (k < 7) {
            xr0 = reinterpret_cast<const float4*>(xsrc + (k + 1) * 32)[0];
            xr1 = reinterpret_cast<const float4*>(xsrc + (k + 1) * 32)[1];
        }
        cp_wait<0>();
        __syncthreads();
        if (k < 7) {
            const uint32_t nboff = (uint32_t)((k + 1) & 1) * ABUF;
            cp16(b_dst + nboff,      bsrc + (k + 1) * 32);
            cp16(b_dst + nboff + 16, bsrc + (k + 1) * 32 + 8);
            cp_commit();
        }

        // ---- MMA: 2 K16 slices x 3 products
#pragma unroll
        for (int ks = 0; ks < 2; ks++) {
            const uint32_t kb = ks * 32;
            uint32_t ahi[2][4], bfr[8];
            ldx4(ahi[0], sbase + OFF_AH + boff + a_off[0] + kb);
            ldx4(ahi[1], sbase + OFF_AH + boff + a_off[1] + kb);
            ldx4(bfr + 0, sbase + OFF_BH + boff + b_off[0] + kb);
            ldx4(bfr + 4, sbase + OFF_BH + boff + b_off[1] + kb);
#pragma unroll
            for (int im = 0; im < 2; im++)
#pragma unroll
                for (int in = 0; in < 4; in++)
                    mma16816(acc[im][in], ahi[im], bfr[in * 2], bfr[in * 2 + 1]);
            // Xlo * Whi
            {
                uint32_t alo[2][4];
                ldx4(alo[0], sbase + OFF_AL + boff + a_off[0] + kb);
                ldx4(alo[1], sbase + OFF_AL + boff + a_off[1] + kb);
#pragma unroll
                for (int im = 0; im < 2; im++)
#pragma unroll
                    for (int in = 0; in < 4; in++)
                        mma16816(acc[im][in], alo[im], bfr[in * 2], bfr[in * 2 + 1]);
            }
            // Xhi * Wlo
            ldx4(bfr + 0, sbase + OFF_BL + boff + b_off[0] + kb);
            ldx4(bfr + 4, sbase + OFF_BL + boff + b_off[1] + kb);
#pragma unroll
            for (int im = 0; im < 2; im++)
#pragma unroll
                for (int in = 0; in < 4; in++)
                    mma16816(acc[im][in], ahi[im], bfr[in * 2], bfr[in * 2 + 1]);
        }
    }
    __syncthreads();

    // ---- epilogue: fp32 + bias -> g_gx
#pragma unroll
    for (int im = 0; im < 2; im++) {
#pragma unroll
        for (int h = 0; h < 2; h++) {
            int m = m0 + warp_m * 32 + im * 16 + h * 8 + (lane >> 2);
            int r = m & (MROWS - 1);
            int t = r >> 8, b = r & 255;
            float* gp = g_gx + (((size_t)cell * LL + t) * BB + b) * G4 + n0;
#pragma unroll
            for (int in = 0; in < 4; in++) {
                int col = warp_n * 32 + in * 8 + (lane & 3) * 2;
                float2 v;
                v.x = acc[im][in][2 * h + 0] + bias_s[col];
                v.y = acc[im][in][2 * h + 1] + bias_s[col + 1];
                *reinterpret_cast<float2*>(gp + col) = v;
            }
        }
    }
}

// ---------------------------------------------------------------------------
// Phase 2: recurrent LSTM — exact R6 version (best measured: 1549 us).
// Cluster of 4 CTAs per chain, 256 threads/CTA, 2 chains co-resident per SM.
// ---------------------------------------------------------------------------
#define HPAD 136
static __device__ __forceinline__ int hidx(int j) { return j + ((j >> 6) << 2); }

__global__ __launch_bounds__(256, 2) __cluster_dims__(4, 1, 1)
void k_recurrent(const float* __restrict__ Whh_h,
                 const float* __restrict__ Whh_f)
{
    __shared__ float h_s[2][TB][HPAD];
    __shared__ float gates_s[128][TB + 1];

    const int tid = threadIdx.x;
    uint32_t rank;
    asm("mov.u32 %0, %%cluster_ctarank;" : "=r"(rank));
    const int q    = blockIdx.x >> 2;
    const int cell = q >> 5;
    const int b0   = (q & 31) * TB;

    const float* W = cell ? Whh_f : Whh_h;

    const int row  = tid >> 1;
    const int half = tid & 1;
    const int g    = row >> 5;
    const int ju   = row & 31;
    const int n    = g * HH + (int)rank * 32 + ju;

    unsigned long long w2[32];
    {
        const float2* wrow = reinterpret_cast<const float2*>(W + (size_t)n * HH + half * 64);
#pragma unroll
        for (int i = 0; i < 32; i++) {
            float2 v = wrow[i];
            w2[i] = pack2(v.x, v.y);
        }
    }

    const int pb = tid >> 5;
    const int pj = tid & 31;
    const int jglob = (int)rank * 32 + pj;
    const uint32_t h_local0 = smem_u32(&h_s[0][pb][hidx(jglob)]);
    const uint32_t h_local1 = smem_u32(&h_s[1][pb][hidx(jglob)]);
    float* hg = g_h + (((size_t)cell * BB + b0 + pb) * LL) * HH + jglob;

    for (int i = tid; i < 2 * TB * HPAD; i += 256) (&h_s[0][0][0])[i] = 0.0f;
    float c_reg = 0.0f;
    __syncthreads();
    asm volatile("barrier.cluster.arrive.aligned;" ::: "memory");
    asm volatile("barrier.cluster.wait.aligned;"   ::: "memory");

    const float* gxbase = g_gx + ((size_t)cell * LL * BB + (b0 + pb)) * G4 + jglob;
    float gxr[4];
#pragma unroll
    for (int gi = 0; gi < 4; gi++)
        gxr[gi] = gxbase[gi * HH];

    int buf = 0;
    for (int t = 0; t < LL; t++) {
#pragma unroll
        for (int bp = 0; bp < TB; bp += 2) {
            const longlong2* hp0 =
                reinterpret_cast<const longlong2*>(&h_s[buf][bp][half * 68]);
            const longlong2* hp1 =
                reinterpret_cast<const longlong2*>(&h_s[buf][bp + 1][half * 68]);
            unsigned long long a00 = 0ull, a01 = 0ull, a10 = 0ull, a11 = 0ull;
#pragma unroll
            for (int i = 0; i < 16; i++) {
                longlong2 v0 = hp0[i];
                longlong2 v1 = hp1[i];
                fma2(a00, (unsigned long long)v0.x, w2[2 * i]);
                fma2(a01, (unsigned long long)v0.y, w2[2 * i + 1]);
                fma2(a10, (unsigned long long)v1.x, w2[2 * i]);
                fma2(a11, (unsigned long long)v1.y, w2[2 * i + 1]);
            }
            float2 s00 = unpack2(a00), s01 = unpack2(a01);
            float2 s10 = unpack2(a10), s11 = unpack2(a11);
            float p0 = (s00.x + s00.y) + (s01.x + s01.y);
            float p1 = (s10.x + s10.y) + (s11.x + s11.y);
            float t0 = p0 + __shfl_xor_sync(0xffffffffu, p0, 1);
            float t1 = p1 + __shfl_xor_sync(0xffffffffu, p1, 1);
            if (!half) {
                gates_s[row][bp]     = t0;
                gates_s[row][bp + 1] = t1;
            }
        }
        __syncthreads();

        float gi_ = gates_s[pj][pb]        + gxr[0];
        float gf_ = gates_s[32 + pj][pb]   + gxr[1];
        float gg_ = gates_s[64 + pj][pb]   + gxr[2];
        float go_ = gates_s[96 + pj][pb]   + gxr[3];
        float ig = sigm(gi_);
        float fg = sigm(gf_);
        float gv = tanha(gg_);
        float og = sigm(go_);
        c_reg = fg * c_reg + ig * gv;
        float hv = og * tanha(c_reg);

        const int nb = buf ^ 1;
        h_s[nb][pb][hidx(jglob)] = hv;
        const uint32_t hla = nb ? h_local1 : h_local0;
#pragma unroll
        for (int r = 1; r < 4; r++)
            st_remote_f32(hla, (rank + r) & 3u, hv);
        hg[(size_t)t * HH] = hv;

        if (t + 1 < LL) {
            const float* gp = gxbase + (size_t)(t + 1) * BB * G4;
#pragma unroll
            for (int gi2 = 0; gi2 < 4; gi2++)
                gxr[gi2] = gp[gi2 * HH];
        }

        asm volatile("barrier.cluster.arrive.aligned;" ::: "memory");
        asm volatile("barrier.cluster.wait.aligned;"   ::: "memory");
        buf = nb;
    }
}

// ---------------------------------------------------------------------------
// Phase 3: y[b][t] = W_ffn . [h_h(b,t); h_f(b,t)] + b_ffn
// ---------------------------------------------------------------------------
__global__ __launch_bounds__(256) void k_finalize(float* __restrict__ out,
                                                  const float* __restrict__ Wffn,
                                                  const float* __restrict__ bffn) {
    __shared__ float wf[2 * HH];
    const int b = blockIdx.x;
    const int tid = threadIdx.x;
    wf[tid] = Wffn[tid];
    __syncthreads();
    const float bias = bffn[0];

    for (int t = tid; t < LL; t += 256) {
        const float4* p0 = reinterpret_cast<const float4*>(
            g_h + (((size_t)0 * BB + b) * LL + t) * HH);
        const float4* p1 = reinterpret_cast<const float4*>(
            g_h + (((size_t)1 * BB + b) * LL + t) * HH);
        float acc = bias;
#pragma unroll 8
        for (int q = 0; q < 32; q++) {
            float4 a = p0[q];
            acc += a.x * wf[4 * q] + a.y * wf[4 * q + 1]
                 + a.z * wf[4 * q + 2] + a.w * wf[4 * q + 3];
        }
#pragma unroll 8
        for (int q = 0; q < 32; q++) {
            float4 a = p1[q];
            acc += a.x * wf[128 + 4 * q] + a.y * wf[128 + 4 * q + 1]
                 + a.z * wf[128 + 4 * q + 2] + a.w * wf[128 + 4 * q + 3];
        }
        out[(size_t)b * LL + t] = acc;
    }
}

// ---------------------------------------------------------------------------
extern "C" void kernel_launch(void* const* d_in, const int* in_sizes, int n_in,
                              void* d_out, int out_size) {
    const float* hist  = (const float*)d_in[0];
    const float* fut   = (const float*)d_in[1];
    const float* Wih_h = (const float*)d_in[2];
    const float* Whh_h = (const float*)d_in[3];
    const float* bih_h = (const float*)d_in[4];
    const float* bhh_h = (const float*)d_in[5];
    const float* Wih_f = (const float*)d_in[6];
    const float* Whh_f = (const float*)d_in[7];
    const float* bih_f = (const float*)d_in[8];
    const float* bhh_f = (const float*)d_in[9];
    const float* Wffn  = (const float*)d_in[10];
    const float* bffn  = (const float*)d_in[11];
    float* out = (float*)d_out;

    static int smem_set = 0;
    if (!smem_set) {
        cudaFuncSetAttribute(k_mma_gemm,
                             cudaFuncAttributeMaxDynamicSharedMemorySize, SMEM_P1);
        smem_set = 1;
    }

    k_convert_w<<<(2 * G4 * 32) / 256, 256>>>(Wih_h, Wih_f);

    dim3 gg(G4 / 128, (2 * MROWS) / 128);   // (4, 2048)
    k_mma_gemm<<<gg, 512, SMEM_P1>>>(hist, fut, bih_h, bhh_h, bih_f, bhh_f);

    k_recurrent<<<256, 256>>>(Whh_h, Whh_f);

    k_finalize<<<BB, 256>>>(out, Wffn, bffn);
}

// round 9
// speedup vs baseline: 1.1742x; 1.0433x over previous
#include <cuda_runtime.h>
#include <cuda_bf16.h>
#include <cstdint>
#include <cstddef>

#define BB   256
#define LL   512
#define EE   256
#define HH   128
#define G4   512
#define TB   8
#define MROWS 131072          // L*B rows per cell
#define WKT  512              // W' width: [hi(256) | lo(256)]

// ---------------------------------------------------------------------------
// Device scratch
// ---------------------------------------------------------------------------
__device__ float g_gx[(size_t)2 * LL * BB * G4];            // 512 MB gates
__device__ __nv_bfloat16 g_wp[(size_t)2 * G4 * WKT];        // 1 MB W' (hi|lo)
__device__ float g_h[(size_t)2 * BB * LL * HH];             // 128 MB hidden states

// ---------------------------------------------------------------------------
// Helpers
// ---------------------------------------------------------------------------
static __device__ __forceinline__ unsigned long long pack2(float x, float y) {
    unsigned long long r;
    asm("mov.b64 %0, {%1, %2};" : "=l"(r) : "f"(x), "f"(y));
    return r;
}
static __device__ __forceinline__ void fma2(unsigned long long& d,
                                            unsigned long long a,
                                            unsigned long long b) {
    asm("fma.rn.f32x2 %0, %1, %2, %0;" : "+l"(d) : "l"(a), "l"(b));
}
static __device__ __forceinline__ float2 unpack2(unsigned long long v) {
    float2 f;
    asm("mov.b64 {%0, %1}, %2;" : "=f"(f.x), "=f"(f.y) : "l"(v));
    return f;
}
static __device__ __forceinline__ uint32_t smem_u32(const void* p) {
    uint32_t a;
    asm("{ .reg .u64 t; cvta.to.shared.u64 t, %1; cvt.u32.u64 %0, t; }"
        : "=r"(a) : "l"(p));
    return a;
}
static __device__ __forceinline__ void st_remote_f32(uint32_t laddr, uint32_t peer, float v) {
    asm volatile(
        "{ .reg .b32 ra; mapa.shared::cluster.u32 ra, %0, %1; "
        "st.shared::cluster.f32 [ra], %2; }"
        :: "r"(laddr), "r"(peer), "f"(v) : "memory");
}
// fast activations (ex2/rcp approx)
static __device__ __forceinline__ float sigm(float x) {
    float t;
    asm("mul.f32 %0, %1, 0fBFB8AA3B;" : "=f"(t) : "f"(x));   // -x*log2(e)
    asm("ex2.approx.f32 %0, %0;" : "+f"(t));
    float r = t + 1.0f;
    asm("rcp.approx.f32 %0, %0;" : "+f"(r));
    return r;
}
static __device__ __forceinline__ float tanha(float x) {
    x = fminf(fmaxf(x, -9.0f), 9.0f);
    float t;
    asm("mul.f32 %0, %1, 0f4038AA3B;" : "=f"(t) : "f"(x));   // 2x*log2(e)
    asm("ex2.approx.f32 %0, %0;" : "+f"(t));                  // e^{2x}
    float den = t + 1.0f;
    asm("rcp.approx.f32 %0, %0;" : "+f"(den));
    return (t - 1.0f) * den;
}
// cp.async
static __device__ __forceinline__ void cp16(uint32_t dst, const void* src) {
    asm volatile("cp.async.cg.shared.global [%0], [%1], 16;"
                 :: "r"(dst), "l"(src) : "memory");
}
static __device__ __forceinline__ void cp_commit() {
    asm volatile("cp.async.commit_group;" ::: "memory");
}
template <int N>
static __device__ __forceinline__ void cp_wait() {
    asm volatile("cp.async.wait_group %0;" :: "n"(N) : "memory");
}
// ldmatrix x4 (b16)
static __device__ __forceinline__ void ldx4(uint32_t* r, uint32_t addr) {
    asm volatile("ldmatrix.sync.aligned.m8n8.x4.shared.b16 {%0,%1,%2,%3}, [%4];"
                 : "=r"(r[0]), "=r"(r[1]), "=r"(r[2]), "=r"(r[3]) : "r"(addr));
}
// bf16 HMMA m16n8k16, fp32 accum
static __device__ __forceinline__ void mma16816(float* c, const uint32_t* a,
                                                uint32_t b0, uint32_t b1) {
    asm volatile(
        "mma.sync.aligned.m16n8k16.row.col.f32.bf16.bf16.f32 "
        "{%0,%1,%2,%3}, {%4,%5,%6,%7}, {%8,%9}, {%0,%1,%2,%3};"
        : "+f"(c[0]), "+f"(c[1]), "+f"(c[2]), "+f"(c[3])
        : "r"(a[0]), "r"(a[1]), "r"(a[2]), "r"(a[3]), "r"(b0), "r"(b1));
}
static __device__ __forceinline__ uint32_t bfpack(__nv_bfloat16 a, __nv_bfloat16 b) {
    return (uint32_t)__bfloat16_as_ushort(a) | ((uint32_t)__bfloat16_as_ushort(b) << 16);
}

// ---------------------------------------------------------------------------
// W' = [hi | lo]  (512 bf16 per row)
// ---------------------------------------------------------------------------
__global__ __launch_bounds__(256) void k_convert_w(const float* __restrict__ Wh,
                                                   const float* __restrict__ Wf) {
    int i = blockIdx.x * 256 + threadIdx.x;               // 2*512*32 total
    int e8 = i & 31;
    int nn = i >> 5;                                      // cell*512 + n
    int cell = nn >> 9;
    int n = nn & 511;
    const float* W = cell ? Wf : Wh;
    const float4* src = reinterpret_cast<const float4*>(W + (size_t)n * EE + e8 * 8);
    float4 v0 = src[0], v1 = src[1];
    float x[8] = {v0.x, v0.y, v0.z, v0.w, v1.x, v1.y, v1.z, v1.w};
    __nv_bfloat16 hi[8], lo[8];
#pragma unroll
    for (int j = 0; j < 8; j++) {
        hi[j] = __float2bfloat16(x[j]);
        lo[j] = __float2bfloat16(x[j] - __bfloat162float(hi[j]));
    }
    uint4 ph, pl;
    ph.x = bfpack(hi[0], hi[1]); ph.y = bfpack(hi[2], hi[3]);
    ph.z = bfpack(hi[4], hi[5]); ph.w = bfpack(hi[6], hi[7]);
    pl.x = bfpack(lo[0], lo[1]); pl.y = bfpack(lo[2], lo[3]);
    pl.z = bfpack(lo[4], lo[5]); pl.w = bfpack(lo[6], lo[7]);
    __nv_bfloat16* dst = g_wp + (size_t)nn * WKT + e8 * 8;
    *reinterpret_cast<uint4*>(dst)       = ph;
    *reinterpret_cast<uint4*>(dst + 256) = pl;
}

// ---------------------------------------------------------------------------
// Phase 1 fused GEMM: Gx = X @ W^T + bias with in-kernel hi/lo split.
// CTA tile M64 x N256, 256 threads (8 warps, warp tile 32x64), K-chunks 32,
// 2 CTAs/SM. 3 sub-products Xhi*Whi + Xlo*Whi + Xhi*Wlo, fp32 accum.
// smem (stride 80B rows):
//   A: [2buf][hi 5120 | lo 5120]                     = 20480
//   B: [2buf][hi 20480 | lo 20480]                   = 81920   (base 20480)
//   bias: 1024 f32 bytes                              (base 102400)
// ---------------------------------------------------------------------------
#define OFF_B   20480
#define OFF_BIAS 102400
#define SMEM_P1 (102400 + 1024)

__global__ __launch_bounds__(256, 2) void k_mma_gemm(
    const float* __restrict__ Xh, const float* __restrict__ Xf,
    const float* __restrict__ bih_h, const float* __restrict__ bhh_h,
    const float* __restrict__ bih_f, const float* __restrict__ bhh_f)
{
    extern __shared__ __align__(16) char smem[];
    const uint32_t sbase = smem_u32(smem);
    float* bias_s = reinterpret_cast<float*>(smem + OFF_BIAS);

    const int tid  = threadIdx.x;
    const int wid  = tid >> 5;
    const int lane = tid & 31;
    const int n0 = blockIdx.x * 256;
    const int m0 = blockIdx.y * 64;
    const int cell = m0 >> 17;

    {
        const float* bi = cell ? bih_f : bih_h;
        const float* bh = cell ? bhh_f : bhh_h;
        bias_s[tid] = bi[n0 + tid] + bh[n0 + tid];
    }

    const float* X = cell ? Xf : Xh;

    // ---- A loader: row = tid>>2 (0..63), quarter = (tid&3)*8 floats
    const int arow = tid >> 2;
    const int aq   = (tid & 3) * 8;
    const int rA = (m0 + arow) & (MROWS - 1);
    const float* xsrc = X + (((size_t)(rA & 255)) * LL + (rA >> 8)) * EE + aq;
    const uint32_t a_sts_h = sbase + arow * 80 + aq * 2;          // + buf*10240
    const uint32_t a_sts_l = a_sts_h + 5120;

    // ---- B loader: 8 cp16/thread/chunk. 2048 cp16 total:
    // idx = tid + i*256; half = idx>>10; r2 = idx&1023; brow = r2>>2; piece = r2&3
    // ---- warp tiling: warp_m = wid&1 (2x32 rows), warp_n = wid>>1 (4x64 cols)
    const int warp_m = wid & 1;
    const int warp_n = wid >> 1;
    uint32_t a_off[2];
#pragma unroll
    for (int im = 0; im < 2; im++)
        a_off[im] = (warp_m * 32 + im * 16 + (lane & 15)) * 80 + (lane >> 4) * 16;
    uint32_t b_off[4];
#pragma unroll
    for (int ip = 0; ip < 4; ip++)
        b_off[ip] = (warp_n * 64 + ip * 16 + (lane >> 4) * 8 + (lane & 7)) * 80
                  + ((lane >> 3) & 1) * 16;

    float acc[2][8][4];
#pragma unroll
    for (int im = 0; im < 2; im++)
#pragma unroll
        for (int in = 0; in < 8; in++)
#pragma unroll
            for (int q = 0; q < 4; q++) acc[im][in][q] = 0.0f;

#define LOAD_B(chunk)                                                          \
    do {                                                                       \
        const int _k0 = (chunk) * 32;                                          \
        const uint32_t _bb = sbase + OFF_B + (uint32_t)((chunk) & 1) * 40960;  \
        _Pragma("unroll")                                                      \
        for (int _i = 0; _i < 8; _i++) {                                       \
            int _idx = tid + _i * 256;                                         \
            int _half = _idx >> 10;                                            \
            int _r2 = _idx & 1023;                                             \
            int _brow = _r2 >> 2;                                              \
            int _pc = _r2 & 3;                                                 \
            cp16(_bb + _half * 20480 + _brow * 80 + _pc * 16,                  \
                 g_wp + ((size_t)cell * G4 + n0 + _brow) * WKT                 \
                      + _half * 256 + _k0 + _pc * 8);                          \
        }                                                                      \
        cp_commit();                                                           \
    } while (0)

    // ---- prologue
    float4 xr0 = reinterpret_cast<const float4*>(xsrc)[0];
    float4 xr1 = reinterpret_cast<const float4*>(xsrc)[1];
    LOAD_B(0);

    for (int k = 0; k < 8; ++k) {
        const uint32_t aboff = (uint32_t)(k & 1) * 10240;
        const uint32_t bboff = (uint32_t)(k & 1) * 40960;

        // convert current X regs -> STS hi/lo
        {
            float x8[8] = {xr0.x, xr0.y, xr0.z, xr0.w, xr1.x, xr1.y, xr1.z, xr1.w};
            __nv_bfloat16 hi[8], lo[8];
#pragma unroll
            for (int j = 0; j < 8; j++) {
                hi[j] = __float2bfloat16(x8[j]);
                lo[j] = __float2bfloat16(x8[j] - __bfloat162float(hi[j]));
            }
            uint4 ph, pl;
            ph.x = bfpack(hi[0], hi[1]); ph.y = bfpack(hi[2], hi[3]);
            ph.z = bfpack(hi[4], hi[5]); ph.w = bfpack(hi[6], hi[7]);
            pl.x = bfpack(lo[0], lo[1]); pl.y = bfpack(lo[2], lo[3]);
            pl.z = bfpack(lo[4], lo[5]); pl.w = bfpack(lo[6], lo[7]);
            asm volatile("st.shared.v4.b32 [%0], {%1,%2,%3,%4};"
                         :: "r"(a_sts_h + aboff), "r"(ph.x), "r"(ph.y), "r"(ph.z), "r"(ph.w)
                         : "memory");
            asm volatile("st.shared.v4.b32 [%0], {%1,%2,%3,%4};"
                         :: "r"(a_sts_l + aboff), "r"(pl.x), "r"(pl.y), "r"(pl.z), "r"(pl.w)
                         : "memory");
        }
        if (k < 7) {
            xr0 = reinterpret_cast<const float4*>(xsrc + (k + 1) * 32)[0];
            xr1 = reinterpret_cast<const float4*>(xsrc + (k + 1) * 32)[1];
        }
        cp_wait<0>();
        __syncthreads();
        if (k < 7) LOAD_B(k + 1);

        // ---- MMA: 2 K16 slices x 3 products
#pragma unroll
        for (int ks = 0; ks < 2; ks++) {
            const uint32_t kb = ks * 32;
            uint32_t ahi[2][4], bfr[16];
            ldx4(ahi[0], sbase + aboff + a_off[0] + kb);
            ldx4(ahi[1], sbase + aboff + a_off[1] + kb);
#pragma unroll
            for (int ip = 0; ip < 4; ip++)
                ldx4(bfr + ip * 4, sbase + OFF_B + bboff + b_off[ip] + kb);
#pragma unroll
            for (int im = 0; im < 2; im++)
#pragma unroll
                for (int in = 0; in < 8; in++)
                    mma16816(acc[im][in], ahi[im], bfr[in * 2], bfr[in * 2 + 1]);
            {
                uint32_t alo[2][4];
                ldx4(alo[0], sbase + aboff + 5120 + a_off[0] + kb);
                ldx4(alo[1], sbase + aboff + 5120 + a_off[1] + kb);
#pragma unroll
                for (int im = 0; im < 2; im++)
#pragma unroll
                    for (int in = 0; in < 8; in++)
                        mma16816(acc[im][in], alo[im], bfr[in * 2], bfr[in * 2 + 1]);
            }
#pragma unroll
            for (int ip = 0; ip < 4; ip++)
                ldx4(bfr + ip * 4, sbase + OFF_B + bboff + 20480 + b_off[ip] + kb);
#pragma unroll
            for (int im = 0; im < 2; im++)
#pragma unroll
                for (int in = 0; in < 8; in++)
                    mma16816(acc[im][in], ahi[im], bfr[in * 2], bfr[in * 2 + 1]);
        }
    }
    __syncthreads();

    // ---- epilogue: fp32 + bias -> g_gx
#pragma unroll
    for (int im = 0; im < 2; im++) {
#pragma unroll
        for (int h = 0; h < 2; h++) {
            int m = m0 + warp_m * 32 + im * 16 + h * 8 + (lane >> 2);
            int r = m & (MROWS - 1);
            int t = r >> 8, b = r & 255;
            float* gp = g_gx + (((size_t)cell * LL + t) * BB + b) * G4 + n0;
#pragma unroll
            for (int in = 0; in < 8; in++) {
                int col = warp_n * 64 + in * 8 + (lane & 3) * 2;
                float2 v;
                v.x = acc[im][in][2 * h + 0] + bias_s[col];
                v.y = acc[im][in][2 * h + 1] + bias_s[col + 1];
                *reinterpret_cast<float2*>(gp + col) = v;
            }
        }
    }
}

// ---------------------------------------------------------------------------
// Phase 2: recurrent LSTM — exact R6 version (measured best). DO NOT TOUCH.
// ---------------------------------------------------------------------------
#define HPAD 136
static __device__ __forceinline__ int hidx(int j) { return j + ((j >> 6) << 2); }

__global__ __launch_bounds__(256, 2) __cluster_dims__(4, 1, 1)
void k_recurrent(const float* __restrict__ Whh_h,
                 const float* __restrict__ Whh_f)
{
    __shared__ float h_s[2][TB][HPAD];
    __shared__ float gates_s[128][TB + 1];

    const int tid = threadIdx.x;
    uint32_t rank;
    asm("mov.u32 %0, %%cluster_ctarank;" : "=r"(rank));
    const int q    = blockIdx.x >> 2;
    const int cell = q >> 5;
    const int b0   = (q & 31) * TB;

    const float* W = cell ? Whh_f : Whh_h;

    const int row  = tid >> 1;
    const int half = tid & 1;
    const int g    = row >> 5;
    const int ju   = row & 31;
    const int n    = g * HH + (int)rank * 32 + ju;

    unsigned long long w2[32];
    {
        const float2* wrow = reinterpret_cast<const float2*>(W + (size_t)n * HH + half * 64);
#pragma unroll
        for (int i = 0; i < 32; i++) {
            float2 v = wrow[i];
            w2[i] = pack2(v.x, v.y);
        }
    }

    const int pb = tid >> 5;
    const int pj = tid & 31;
    const int jglob = (int)rank * 32 + pj;
    const uint32_t h_local0 = smem_u32(&h_s[0][pb][hidx(jglob)]);
    const uint32_t h_local1 = smem_u32(&h_s[1][pb][hidx(jglob)]);
    float* hg = g_h + (((size_t)cell * BB + b0 + pb) * LL) * HH + jglob;

    for (int i = tid; i < 2 * TB * HPAD; i += 256) (&h_s[0][0][0])[i] = 0.0f;
    float c_reg = 0.0f;
    __syncthreads();
    asm volatile("barrier.cluster.arrive.aligned;" ::: "memory");
    asm volatile("barrier.cluster.wait.aligned;"   ::: "memory");

    const float* gxbase = g_gx + ((size_t)cell * LL * BB + (b0 + pb)) * G4 + jglob;
    float gxr[4];
#pragma unroll
    for (int gi = 0; gi < 4; gi++)
        gxr[gi] = gxbase[gi * HH];

    int buf = 0;
    for (int t = 0; t < LL; t++) {
#pragma unroll
        for (int bp = 0; bp < TB; bp += 2) {
            const longlong2* hp0 =
                reinterpret_cast<const longlong2*>(&h_s[buf][bp][half * 68]);
            const longlong2* hp1 =
                reinterpret_cast<const longlong2*>(&h_s[buf][bp + 1][half * 68]);
            unsigned long long a00 = 0ull, a01 = 0ull, a10 = 0ull, a11 = 0ull;
#pragma unroll
            for (int i = 0; i < 16; i++) {
                longlong2 v0 = hp0[i];
                longlong2 v1 = hp1[i];
                fma2(a00, (unsigned long long)v0.x, w2[2 * i]);
                fma2(a01, (unsigned long long)v0.y, w2[2 * i + 1]);
                fma2(a10, (unsigned long long)v1.x, w2[2 * i]);
                fma2(a11, (unsigned long long)v1.y, w2[2 * i + 1]);
            }
            float2 s00 = unpack2(a00), s01 = unpack2(a01);
            float2 s10 = unpack2(a10), s11 = unpack2(a11);
            float p0 = (s00.x + s00.y) + (s01.x + s01.y);
            float p1 = (s10.x + s10.y) + (s11.x + s11.y);
            float t0 = p0 + __shfl_xor_sync(0xffffffffu, p0, 1);
            float t1 = p1 + __shfl_xor_sync(0xffffffffu, p1, 1);
            if (!half) {
                gates_s[row][bp]     = t0;
                gates_s[row][bp + 1] = t1;
            }
        }
        __syncthreads();

        float gi_ = gates_s[pj][pb]        + gxr[0];
        float gf_ = gates_s[32 + pj][pb]   + gxr[1];
        float gg_ = gates_s[64 + pj][pb]   + gxr[2];
        float go_ = gates_s[96 + pj][pb]   + gxr[3];
        float ig = sigm(gi_);
        float fg = sigm(gf_);
        float gv = tanha(gg_);
        float og = sigm(go_);
        c_reg = fg * c_reg + ig * gv;
        float hv = og * tanha(c_reg);

        const int nb = buf ^ 1;
        h_s[nb][pb][hidx(jglob)] = hv;
        const uint32_t hla = nb ? h_local1 : h_local0;
#pragma unroll
        for (int r = 1; r < 4; r++)
            st_remote_f32(hla, (rank + r) & 3u, hv);
        hg[(size_t)t * HH] = hv;

        if (t + 1 < LL) {
            const float* gp = gxbase + (size_t)(t + 1) * BB * G4;
#pragma unroll
            for (int gi2 = 0; gi2 < 4; gi2++)
                gxr[gi2] = gp[gi2 * HH];
        }

        asm volatile("barrier.cluster.arrive.aligned;" ::: "memory");
        asm volatile("barrier.cluster.wait.aligned;"   ::: "memory");
        buf = nb;
    }
}

// ---------------------------------------------------------------------------
// Phase 3: y[b][t] = W_ffn . [h_h(b,t); h_f(b,t)] + b_ffn
// grid 512: block = (b, t-half); one t per thread.
// ---------------------------------------------------------------------------
__global__ __launch_bounds__(256) void k_finalize(float* __restrict__ out,
                                                  const float* __restrict__ Wffn,
                                                  const float* __restrict__ bffn) {
    __shared__ float wf[2 * HH];
    const int b = blockIdx.x >> 1;
    const int t = (blockIdx.x & 1) * 256 + threadIdx.x;
    wf[threadIdx.x] = Wffn[threadIdx.x];
    __syncthreads();
    const float bias = bffn[0];

    const float4* p0 = reinterpret_cast<const float4*>(
        g_h + (((size_t)0 * BB + b) * LL + t) * HH);
    const float4* p1 = reinterpret_cast<const float4*>(
        g_h + (((size_t)1 * BB + b) * LL + t) * HH);
    float acc = bias;
#pragma unroll 8
    for (int q = 0; q < 32; q++) {
        float4 a = p0[q];
        acc += a.x * wf[4 * q] + a.y * wf[4 * q + 1]
             + a.z * wf[4 * q + 2] + a.w * wf[4 * q + 3];
    }
#pragma unroll 8
    for (int q = 0; q < 32; q++) {
        float4 a = p1[q];
        acc += a.x * wf[128 + 4 * q] + a.y * wf[128 + 4 * q + 1]
             + a.z * wf[128 + 4 * q + 2] + a.w * wf[128 + 4 * q + 3];
    }
    out[(size_t)b * LL + t] = acc;
}

// ---------------------------------------------------------------------------
extern "C" void kernel_launch(void* const* d_in, const int* in_sizes, int n_in,
                              void* d_out, int out_size) {
    const float* hist  = (const float*)d_in[0];
    const float* fut   = (const float*)d_in[1];
    const float* Wih_h = (const float*)d_in[2];
    const float* Whh_h = (const float*)d_in[3];
    const float* bih_h = (const float*)d_in[4];
    const float* bhh_h = (const float*)d_in[5];
    const float* Wih_f = (const float*)d_in[6];
    const float* Whh_f = (const float*)d_in[7];
    const float* bih_f = (const float*)d_in[8];
    const float* bhh_f = (const float*)d_in[9];
    const float* Wffn  = (const float*)d_in[10];
    const float* bffn  = (const float*)d_in[11];
    float* out = (float*)d_out;

    static int smem_set = 0;
    if (!smem_set) {
        cudaFuncSetAttribute(k_mma_gemm,
                             cudaFuncAttributeMaxDynamicSharedMemorySize, SMEM_P1);
        smem_set = 1;
    }

    k_convert_w<<<(2 * G4 * 32) / 256, 256>>>(Wih_h, Wih_f);

    dim3 gg(G4 / 256, (2 * MROWS) / 64);   // (2, 4096)
    k_mma_gemm<<<gg, 256, SMEM_P1>>>(hist, fut, bih_h, bhh_h, bih_f, bhh_f);

    k_recurrent<<<256, 256>>>(Whh_h, Whh_f);

    k_finalize<<<2 * BB, 256>>>(out, Wffn, bffn);
}

// round 10
// speedup vs baseline: 1.3092x; 1.1150x over previous
#include <cuda_runtime.h>
#include <cuda_bf16.h>
#include <cstdint>
#include <cstddef>

#define BB   256
#define LL   512
#define EE   256
#define HH   128
#define G4   512
#define TB   8
#define MROWS 131072          // L*B rows per cell
#define WKT  512              // W' width: [hi(256) | lo(256)]

// ---------------------------------------------------------------------------
// Device scratch
// ---------------------------------------------------------------------------
__device__ float g_gx[(size_t)2 * LL * BB * G4];            // 512 MB gates
__device__ __nv_bfloat16 g_wp[(size_t)2 * G4 * WKT];        // 1 MB W' (hi|lo)
__device__ float g_h[(size_t)2 * BB * LL * HH];             // 128 MB hidden states

// ---------------------------------------------------------------------------
// Helpers
// ---------------------------------------------------------------------------
static __device__ __forceinline__ unsigned long long pack2(float x, float y) {
    unsigned long long r;
    asm("mov.b64 %0, {%1, %2};" : "=l"(r) : "f"(x), "f"(y));
    return r;
}
static __device__ __forceinline__ void fma2(unsigned long long& d,
                                            unsigned long long a,
                                            unsigned long long b) {
    asm("fma.rn.f32x2 %0, %1, %2, %0;" : "+l"(d) : "l"(a), "l"(b));
}
static __device__ __forceinline__ float2 unpack2(unsigned long long v) {
    float2 f;
    asm("mov.b64 {%0, %1}, %2;" : "=f"(f.x), "=f"(f.y) : "l"(v));
    return f;
}
static __device__ __forceinline__ uint32_t smem_u32(const void* p) {
    uint32_t a;
    asm("{ .reg .u64 t; cvta.to.shared.u64 t, %1; cvt.u32.u64 %0, t; }"
        : "=r"(a) : "l"(p));
    return a;
}
static __device__ __forceinline__ void st_remote_f32(uint32_t laddr, uint32_t peer, float v) {
    asm volatile(
        "{ .reg .b32 ra; mapa.shared::cluster.u32 ra, %0, %1; "
        "st.shared::cluster.f32 [ra], %2; }"
        :: "r"(laddr), "r"(peer), "f"(v) : "memory");
}
// fast activations (ex2/rcp approx)
static __device__ __forceinline__ float sigm(float x) {
    float t;
    asm("mul.f32 %0, %1, 0fBFB8AA3B;" : "=f"(t) : "f"(x));   // -x*log2(e)
    asm("ex2.approx.f32 %0, %0;" : "+f"(t));
    float r = t + 1.0f;
    asm("rcp.approx.f32 %0, %0;" : "+f"(r));
    return r;
}
static __device__ __forceinline__ float tanha(float x) {
    x = fminf(fmaxf(x, -9.0f), 9.0f);
    float t;
    asm("mul.f32 %0, %1, 0f4038AA3B;" : "=f"(t) : "f"(x));   // 2x*log2(e)
    asm("ex2.approx.f32 %0, %0;" : "+f"(t));                  // e^{2x}
    float den = t + 1.0f;
    asm("rcp.approx.f32 %0, %0;" : "+f"(den));
    return (t - 1.0f) * den;
}
// cp.async
static __device__ __forceinline__ void cp16(uint32_t dst, const void* src) {
    asm volatile("cp.async.cg.shared.global [%0], [%1], 16;"
                 :: "r"(dst), "l"(src) : "memory");
}
static __device__ __forceinline__ void cp_commit() {
    asm volatile("cp.async.commit_group;" ::: "memory");
}
template <int N>
static __device__ __forceinline__ void cp_wait() {
    asm volatile("cp.async.wait_group %0;" :: "n"(N) : "memory");
}
// ldmatrix x4 (b16)
static __device__ __forceinline__ void ldx4(uint32_t* r, uint32_t addr) {
    asm volatile("ldmatrix.sync.aligned.m8n8.x4.shared.b16 {%0,%1,%2,%3}, [%4];"
                 : "=r"(r[0]), "=r"(r[1]), "=r"(r[2]), "=r"(r[3]) : "r"(addr));
}
// bf16 HMMA m16n8k16, fp32 accum
static __device__ __forceinline__ void mma16816(float* c, const uint32_t* a,
                                                uint32_t b0, uint32_t b1) {
    asm volatile(
        "mma.sync.aligned.m16n8k16.row.col.f32.bf16.bf16.f32 "
        "{%0,%1,%2,%3}, {%4,%5,%6,%7}, {%8,%9}, {%0,%1,%2,%3};"
        : "+f"(c[0]), "+f"(c[1]), "+f"(c[2]), "+f"(c[3])
        : "r"(a[0]), "r"(a[1]), "r"(a[2]), "r"(a[3]), "r"(b0), "r"(b1));
}
static __device__ __forceinline__ uint32_t bfpack(__nv_bfloat16 a, __nv_bfloat16 b) {
    return (uint32_t)__bfloat16_as_ushort(a) | ((uint32_t)__bfloat16_as_ushort(b) << 16);
}

// ---------------------------------------------------------------------------
// W' = [hi | lo]  (512 bf16 per row)
// ---------------------------------------------------------------------------
__global__ __launch_bounds__(256) void k_convert_w(const float* __restrict__ Wh,
                                                   const float* __restrict__ Wf) {
    int i = blockIdx.x * 256 + threadIdx.x;               // 2*512*32 total
    int e8 = i & 31;
    int nn = i >> 5;                                      // cell*512 + n
    int cell = nn >> 9;
    int n = nn & 511;
    const float* W = cell ? Wf : Wh;
    const float4* src = reinterpret_cast<const float4*>(W + (size_t)n * EE + e8 * 8);
    float4 v0 = src[0], v1 = src[1];
    float x[8] = {v0.x, v0.y, v0.z, v0.w, v1.x, v1.y, v1.z, v1.w};
    __nv_bfloat16 hi[8], lo[8];
#pragma unroll
    for (int j = 0; j < 8; j++) {
        hi[j] = __float2bfloat16(x[j]);
        lo[j] = __float2bfloat16(x[j] - __bfloat162float(hi[j]));
    }
    uint4 ph, pl;
    ph.x = bfpack(hi[0], hi[1]); ph.y = bfpack(hi[2], hi[3]);
    ph.z = bfpack(hi[4], hi[5]); ph.w = bfpack(hi[6], hi[7]);
    pl.x = bfpack(lo[0], lo[1]); pl.y = bfpack(lo[2], lo[3]);
    pl.z = bfpack(lo[4], lo[5]); pl.w = bfpack(lo[6], lo[7]);
    __nv_bfloat16* dst = g_wp + (size_t)nn * WKT + e8 * 8;
    *reinterpret_cast<uint4*>(dst)       = ph;
    *reinterpret_cast<uint4*>(dst + 256) = pl;
}

// ---------------------------------------------------------------------------
// Phase 1 fused GEMM (unchanged from R9 — validated, 2 CTAs/SM, M64xN256)
// ---------------------------------------------------------------------------
#define OFF_B   20480
#define OFF_BIAS 102400
#define SMEM_P1 (102400 + 1024)

__global__ __launch_bounds__(256, 2) void k_mma_gemm(
    const float* __restrict__ Xh, const float* __restrict__ Xf,
    const float* __restrict__ bih_h, const float* __restrict__ bhh_h,
    const float* __restrict__ bih_f, const float* __restrict__ bhh_f)
{
    extern __shared__ __align__(16) char smem[];
    const uint32_t sbase = smem_u32(smem);
    float* bias_s = reinterpret_cast<float*>(smem + OFF_BIAS);

    const int tid  = threadIdx.x;
    const int wid  = tid >> 5;
    const int lane = tid & 31;
    const int n0 = blockIdx.x * 256;
    const int m0 = blockIdx.y * 64;
    const int cell = m0 >> 17;

    {
        const float* bi = cell ? bih_f : bih_h;
        const float* bh = cell ? bhh_f : bhh_h;
        bias_s[tid] = bi[n0 + tid] + bh[n0 + tid];
    }

    const float* X = cell ? Xf : Xh;

    const int arow = tid >> 2;
    const int aq   = (tid & 3) * 8;
    const int rA = (m0 + arow) & (MROWS - 1);
    const float* xsrc = X + (((size_t)(rA & 255)) * LL + (rA >> 8)) * EE + aq;
    const uint32_t a_sts_h = sbase + arow * 80 + aq * 2;
    const uint32_t a_sts_l = a_sts_h + 5120;

    const int warp_m = wid & 1;
    const int warp_n = wid >> 1;
    uint32_t a_off[2];
#pragma unroll
    for (int im = 0; im < 2; im++)
        a_off[im] = (warp_m * 32 + im * 16 + (lane & 15)) * 80 + (lane >> 4) * 16;
    uint32_t b_off[4];
#pragma unroll
    for (int ip = 0; ip < 4; ip++)
        b_off[ip] = (warp_n * 64 + ip * 16 + (lane >> 4) * 8 + (lane & 7)) * 80
                  + ((lane >> 3) & 1) * 16;

    float acc[2][8][4];
#pragma unroll
    for (int im = 0; im < 2; im++)
#pragma unroll
        for (int in = 0; in < 8; in++)
#pragma unroll
            for (int q = 0; q < 4; q++) acc[im][in][q] = 0.0f;

#define LOAD_B(chunk)                                                          \
    do {                                                                       \
        const int _k0 = (chunk) * 32;                                          \
        const uint32_t _bb = sbase + OFF_B + (uint32_t)((chunk) & 1) * 40960;  \
        _Pragma("unroll")                                                      \
        for (int _i = 0; _i < 8; _i++) {                                       \
            int _idx = tid + _i * 256;                                         \
            int _half = _idx >> 10;                                            \
            int _r2 = _idx & 1023;                                             \
            int _brow = _r2 >> 2;                                              \
            int _pc = _r2 & 3;                                                 \
            cp16(_bb + _half * 20480 + _brow * 80 + _pc * 16,                  \
                 g_wp + ((size_t)cell * G4 + n0 + _brow) * WKT                 \
                      + _half * 256 + _k0 + _pc * 8);                          \
        }                                                                      \
        cp_commit();                                                           \
    } while (0)

    float4 xr0 = reinterpret_cast<const float4*>(xsrc)[0];
    float4 xr1 = reinterpret_cast<const float4*>(xsrc)[1];
    LOAD_B(0);

    for (int k = 0; k < 8; ++k) {
        const uint32_t aboff = (uint32_t)(k & 1) * 10240;
        const uint32_t bboff = (uint32_t)(k & 1) * 40960;

        {
            float x8[8] = {xr0.x, xr0.y, xr0.z, xr0.w, xr1.x, xr1.y, xr1.z, xr1.w};
            __nv_bfloat16 hi[8], lo[8];
#pragma unroll
            for (int j = 0; j < 8; j++) {
                hi[j] = __float2bfloat16(x8[j]);
                lo[j] = __float2bfloat16(x8[j] - __bfloat162float(hi[j]));
            }
            uint4 ph, pl;
            ph.x = bfpack(hi[0], hi[1]); ph.y = bfpack(hi[2], hi[3]);
            ph.z = bfpack(hi[4], hi[5]); ph.w = bfpack(hi[6], hi[7]);
            pl.x = bfpack(lo[0], lo[1]); pl.y = bfpack(lo[2], lo[3]);
            pl.z = bfpack(lo[4], lo[5]); pl.w = bfpack(lo[6], lo[7]);
            asm volatile("st.shared.v4.b32 [%0], {%1,%2,%3,%4};"
                         :: "r"(a_sts_h + aboff), "r"(ph.x), "r"(ph.y), "r"(ph.z), "r"(ph.w)
                         : "memory");
            asm volatile("st.shared.v4.b32 [%0], {%1,%2,%3,%4};"
                         :: "r"(a_sts_l + aboff), "r"(pl.x), "r"(pl.y), "r"(pl.z), "r"(pl.w)
                         : "memory");
        }
        if (k < 7) {
            xr0 = reinterpret_cast<const float4*>(xsrc + (k + 1) * 32)[0];
            xr1 = reinterpret_cast<const float4*>(xsrc + (k + 1) * 32)[1];
        }
        cp_wait<0>();
        __syncthreads();
        if (k < 7) LOAD_B(k + 1);

#pragma unroll
        for (int ks = 0; ks < 2; ks++) {
            const uint32_t kb = ks * 32;
            uint32_t ahi[2][4], bfr[16];
            ldx4(ahi[0], sbase + aboff + a_off[0] + kb);
            ldx4(ahi[1], sbase + aboff + a_off[1] + kb);
#pragma unroll
            for (int ip = 0; ip < 4; ip++)
                ldx4(bfr + ip * 4, sbase + OFF_B + bboff + b_off[ip] + kb);
#pragma unroll
            for (int im = 0; im < 2; im++)
#pragma unroll
                for (int in = 0; in < 8; in++)
                    mma16816(acc[im][in], ahi[im], bfr[in * 2], bfr[in * 2 + 1]);
            {
                uint32_t alo[2][4];
                ldx4(alo[0], sbase + aboff + 5120 + a_off[0] + kb);
                ldx4(alo[1], sbase + aboff + 5120 + a_off[1] + kb);
#pragma unroll
                for (int im = 0; im < 2; im++)
#pragma unroll
                    for (int in = 0; in < 8; in++)
                        mma16816(acc[im][in], alo[im], bfr[in * 2], bfr[in * 2 + 1]);
            }
#pragma unroll
            for (int ip = 0; ip < 4; ip++)
                ldx4(bfr + ip * 4, sbase + OFF_B + bboff + 20480 + b_off[ip] + kb);
#pragma unroll
            for (int im = 0; im < 2; im++)
#pragma unroll
                for (int in = 0; in < 8; in++)
                    mma16816(acc[im][in], ahi[im], bfr[in * 2], bfr[in * 2 + 1]);
        }
    }
    __syncthreads();

#pragma unroll
    for (int im = 0; im < 2; im++) {
#pragma unroll
        for (int h = 0; h < 2; h++) {
            int m = m0 + warp_m * 32 + im * 16 + h * 8 + (lane >> 2);
            int r = m & (MROWS - 1);
            int t = r >> 8, b = r & 255;
            float* gp = g_gx + (((size_t)cell * LL + t) * BB + b) * G4 + n0;
#pragma unroll
            for (int in = 0; in < 8; in++) {
                int col = warp_n * 64 + in * 8 + (lane & 3) * 2;
                float2 v;
                v.x = acc[im][in][2 * h + 0] + bias_s[col];
                v.y = acc[im][in][2 * h + 1] + bias_s[col + 1];
                *reinterpret_cast<float2*>(gp + col) = v;
            }
        }
    }
}

// ---------------------------------------------------------------------------
// Phase 2: recurrent LSTM v2 — same R6 skeleton (cluster 4, 256 thr, 2/SM,
// DSMEM broadcast + cluster barrier), matvec retiled for h-reuse:
// thread owns (2 rows x 32-K quarter), all 8 batches. K-quarter lives in the
// WARP index so every h load is warp-uniform (1 crossbar cycle). Cross-quarter
// reduce via smem partials gq[4][128][9] (replaces shfl).
// ---------------------------------------------------------------------------
#define HPAD 136
static __device__ __forceinline__ int hidx(int j) { return j + ((j >> 6) << 2); }

__global__ __launch_bounds__(256, 2) __cluster_dims__(4, 1, 1)
void k_recurrent(const float* __restrict__ Whh_h,
                 const float* __restrict__ Whh_f)
{
    __shared__ float h_s[2][TB][HPAD];      // 8.7 KB
    __shared__ float gq[4][128][9];         // 18 KB partials [Kq][row][b]

    const int tid = threadIdx.x;
    uint32_t rank;
    asm("mov.u32 %0, %%cluster_ctarank;" : "=r"(rank));
    const int q    = blockIdx.x >> 2;
    const int cell = q >> 5;
    const int b0   = (q & 31) * TB;

    const float* W = cell ? Whh_f : Whh_h;

    // ---- matvec tile: warp w = [Kq(2b) | rp_hi(1b)], lane -> rp_low
    const int w  = tid >> 5;
    const int l  = tid & 31;
    const int Kq = w >> 1;                  // 0..3 (K quarter, per-warp)
    const int rp = ((w & 1) << 5) | l;      // 0..63 row pair
    const int r0 = 2 * rp;                  // local rows r0, r0+1
    const int gg = r0 >> 5;                 // gate group (same for r0, r0+1)
    const int nr0 = gg * HH + (int)rank * 32 + (r0 & 31);
    const int nr1 = gg * HH + (int)rank * 32 + ((r0 + 1) & 31);
    const int koff = Kq * 32 + ((Kq >> 1) << 2);   // h_s offset incl. pad

    unsigned long long w2a[16], w2b[16];    // 2 rows x 32 K floats = 64 regs
    {
        const float2* wr0 = reinterpret_cast<const float2*>(W + (size_t)nr0 * HH + Kq * 32);
        const float2* wr1 = reinterpret_cast<const float2*>(W + (size_t)nr1 * HH + Kq * 32);
#pragma unroll
        for (int i = 0; i < 16; i++) {
            float2 a = wr0[i]; w2a[i] = pack2(a.x, a.y);
            float2 b = wr1[i]; w2b[i] = pack2(b.x, b.y);
        }
    }

    // ---- pointwise mapping (identical to R6)
    const int pb = tid >> 5;
    const int pj = tid & 31;
    const int jglob = (int)rank * 32 + pj;
    const uint32_t h_local0 = smem_u32(&h_s[0][pb][hidx(jglob)]);
    const uint32_t h_local1 = smem_u32(&h_s[1][pb][hidx(jglob)]);
    float* hg = g_h + (((size_t)cell * BB + b0 + pb) * LL) * HH + jglob;

    for (int i = tid; i < 2 * TB * HPAD; i += 256) (&h_s[0][0][0])[i] = 0.0f;
    float c_reg = 0.0f;
    __syncthreads();
    asm volatile("barrier.cluster.arrive.aligned;" ::: "memory");
    asm volatile("barrier.cluster.wait.aligned;"   ::: "memory");

    const float* gxbase = g_gx + ((size_t)cell * LL * BB + (b0 + pb)) * G4 + jglob;
    float gxr[4];
#pragma unroll
    for (int gi = 0; gi < 4; gi++)
        gxr[gi] = gxbase[gi * HH];

    int buf = 0;
    for (int t = 0; t < LL; t++) {
        // ---- matvec: per batch, 8 uniform LDS.128 + 32 fma2 (2 rows)
#pragma unroll
        for (int b = 0; b < TB; b++) {
            const longlong2* hp =
                reinterpret_cast<const longlong2*>(&h_s[buf][b][koff]);
            unsigned long long a0 = 0ull, a1 = 0ull;
#pragma unroll
            for (int i = 0; i < 8; i++) {
                longlong2 v = hp[i];
                fma2(a0, (unsigned long long)v.x, w2a[2 * i]);
                fma2(a0, (unsigned long long)v.y, w2a[2 * i + 1]);
                fma2(a1, (unsigned long long)v.x, w2b[2 * i]);
                fma2(a1, (unsigned long long)v.y, w2b[2 * i + 1]);
            }
            float2 s0 = unpack2(a0);
            float2 s1 = unpack2(a1);
            gq[Kq][r0][b]     = s0.x + s0.y;
            gq[Kq][r0 + 1][b] = s1.x + s1.y;
        }
        __syncthreads();

        // ---- reduce quarters + pointwise: unit (pb, jglob)
        float gv4[4];
#pragma unroll
        for (int gi = 0; gi < 4; gi++) {
            int r = gi * 32 + pj;
            gv4[gi] = ((gq[0][r][pb] + gq[1][r][pb])
                     + (gq[2][r][pb] + gq[3][r][pb])) + gxr[gi];
        }
        float ig = sigm(gv4[0]);
        float fg = sigm(gv4[1]);
        float gv = tanha(gv4[2]);
        float og = sigm(gv4[3]);
        c_reg = fg * c_reg + ig * gv;
        float hv = og * tanha(c_reg);

        const int nb = buf ^ 1;
        h_s[nb][pb][hidx(jglob)] = hv;
        const uint32_t hla = nb ? h_local1 : h_local0;
#pragma unroll
        for (int r = 1; r < 4; r++)
            st_remote_f32(hla, (rank + r) & 3u, hv);
        hg[(size_t)t * HH] = hv;

        if (t + 1 < LL) {
            const float* gp = gxbase + (size_t)(t + 1) * BB * G4;
#pragma unroll
            for (int gi2 = 0; gi2 < 4; gi2++)
                gxr[gi2] = gp[gi2 * HH];
        }

        asm volatile("barrier.cluster.arrive.aligned;" ::: "memory");
        asm volatile("barrier.cluster.wait.aligned;"   ::: "memory");
        buf = nb;
    }
}

// ---------------------------------------------------------------------------
// Phase 3: y[b][t] = W_ffn . [h_h(b,t); h_f(b,t)] + b_ffn  (R9 version)
// ---------------------------------------------------------------------------
__global__ __launch_bounds__(256) void k_finalize(float* __restrict__ out,
                                                  const float* __restrict__ Wffn,
                                                  const float* __restrict__ bffn) {
    __shared__ float wf[2 * HH];
    const int b = blockIdx.x >> 1;
    const int t = (blockIdx.x & 1) * 256 + threadIdx.x;
    wf[threadIdx.x] = Wffn[threadIdx.x];
    __syncthreads();
    const float bias = bffn[0];

    const float4* p0 = reinterpret_cast<const float4*>(
        g_h + (((size_t)0 * BB + b) * LL + t) * HH);
    const float4* p1 = reinterpret_cast<const float4*>(
        g_h + (((size_t)1 * BB + b) * LL + t) * HH);
    float acc = bias;
#pragma unroll 8
    for (int q = 0; q < 32; q++) {
        float4 a = p0[q];
        acc += a.x * wf[4 * q] + a.y * wf[4 * q + 1]
             + a.z * wf[4 * q + 2] + a.w * wf[4 * q + 3];
    }
#pragma unroll 8
    for (int q = 0; q < 32; q++) {
        float4 a = p1[q];
        acc += a.x * wf[128 + 4 * q] + a.y * wf[128 + 4 * q + 1]
             + a.z * wf[128 + 4 * q + 2] + a.w * wf[128 + 4 * q + 3];
    }
    out[(size_t)b * LL + t] = acc;
}

// ---------------------------------------------------------------------------
extern "C" void kernel_launch(void* const* d_in, const int* in_sizes, int n_in,
                              void* d_out, int out_size) {
    const float* hist  = (const float*)d_in[0];
    const float* fut   = (const float*)d_in[1];
    const float* Wih_h = (const float*)d_in[2];
    const float* Whh_h = (const float*)d_in[3];
    const float* bih_h = (const float*)d_in[4];
    const float* bhh_h = (const float*)d_in[5];
    const float* Wih_f = (const float*)d_in[6];
    const float* Whh_f = (const float*)d_in[7];
    const float* bih_f = (const float*)d_in[8];
    const float* bhh_f = (const float*)d_in[9];
    const float* Wffn  = (const float*)d_in[10];
    const float* bffn  = (const float*)d_in[11];
    float* out = (float*)d_out;

    static int smem_set = 0;
    if (!smem_set) {
        cudaFuncSetAttribute(k_mma_gemm,
                             cudaFuncAttributeMaxDynamicSharedMemorySize, SMEM_P1);
        smem_set = 1;
    }

    k_convert_w<<<(2 * G4 * 32) / 256, 256>>>(Wih_h, Wih_f);

    dim3 gg(G4 / 256, (2 * MROWS) / 64);   // (2, 4096)
    k_mma_gemm<<<gg, 256, SMEM_P1>>>(hist, fut, bih_h, bhh_h, bih_f, bhh_f);

    k_recurrent<<<256, 256>>>(Whh_h, Whh_f);

    k_finalize<<<2 * BB, 256>>>(out, Wffn, bffn);
}

// round 11
// speedup vs baseline: 1.7586x; 1.3433x over previous
#include <cuda_runtime.h>
#include <cuda_bf16.h>
#include <cstdint>
#include <cstddef>

#define BB   256
#define LL   512
#define EE   256
#define HH   128
#define G4   512
#define TB   8
#define MROWS 131072          // L*B rows per cell
#define WKT  512              // W' width: [hi(256) | lo(256)]

// ---------------------------------------------------------------------------
// Device scratch
// ---------------------------------------------------------------------------
__device__ float g_gx[(size_t)2 * LL * BB * G4];            // 512 MB gates
__device__ __nv_bfloat16 g_wp[(size_t)2 * G4 * WKT];        // 1 MB W' (hi|lo)
__device__ float g_h[(size_t)2 * BB * LL * HH];             // 128 MB hidden states

// ---------------------------------------------------------------------------
// Helpers
// ---------------------------------------------------------------------------
static __device__ __forceinline__ uint32_t smem_u32(const void* p) {
    uint32_t a;
    asm("{ .reg .u64 t; cvta.to.shared.u64 t, %1; cvt.u32.u64 %0, t; }"
        : "=r"(a) : "l"(p));
    return a;
}
static __device__ __forceinline__ void st_remote_b16(uint32_t laddr, uint32_t peer,
                                                     uint16_t v) {
    asm volatile(
        "{ .reg .b32 ra; mapa.shared::cluster.u32 ra, %0, %1; "
        "st.shared::cluster.b16 [ra], %2; }"
        :: "r"(laddr), "r"(peer), "h"(v) : "memory");
}
// fast activations (ex2/rcp approx)
static __device__ __forceinline__ float sigm(float x) {
    float t;
    asm("mul.f32 %0, %1, 0fBFB8AA3B;" : "=f"(t) : "f"(x));   // -x*log2(e)
    asm("ex2.approx.f32 %0, %0;" : "+f"(t));
    float r = t + 1.0f;
    asm("rcp.approx.f32 %0, %0;" : "+f"(r));
    return r;
}
static __device__ __forceinline__ float tanha(float x) {
    x = fminf(fmaxf(x, -9.0f), 9.0f);
    float t;
    asm("mul.f32 %0, %1, 0f4038AA3B;" : "=f"(t) : "f"(x));   // 2x*log2(e)
    asm("ex2.approx.f32 %0, %0;" : "+f"(t));                  // e^{2x}
    float den = t + 1.0f;
    asm("rcp.approx.f32 %0, %0;" : "+f"(den));
    return (t - 1.0f) * den;
}
// cp.async
static __device__ __forceinline__ void cp16(uint32_t dst, const void* src) {
    asm volatile("cp.async.cg.shared.global [%0], [%1], 16;"
                 :: "r"(dst), "l"(src) : "memory");
}
static __device__ __forceinline__ void cp_commit() {
    asm volatile("cp.async.commit_group;" ::: "memory");
}
template <int N>
static __device__ __forceinline__ void cp_wait() {
    asm volatile("cp.async.wait_group %0;" :: "n"(N) : "memory");
}
// ldmatrix x4 (b16)
static __device__ __forceinline__ void ldx4(uint32_t* r, uint32_t addr) {
    asm volatile("ldmatrix.sync.aligned.m8n8.x4.shared.b16 {%0,%1,%2,%3}, [%4];"
                 : "=r"(r[0]), "=r"(r[1]), "=r"(r[2]), "=r"(r[3]) : "r"(addr));
}
// bf16 HMMA m16n8k16, fp32 accum
static __device__ __forceinline__ void mma16816(float* c, const uint32_t* a,
                                                uint32_t b0, uint32_t b1) {
    asm volatile(
        "mma.sync.aligned.m16n8k16.row.col.f32.bf16.bf16.f32 "
        "{%0,%1,%2,%3}, {%4,%5,%6,%7}, {%8,%9}, {%0,%1,%2,%3};"
        : "+f"(c[0]), "+f"(c[1]), "+f"(c[2]), "+f"(c[3])
        : "r"(a[0]), "r"(a[1]), "r"(a[2]), "r"(a[3]), "r"(b0), "r"(b1));
}
static __device__ __forceinline__ uint32_t bfpack(__nv_bfloat16 a, __nv_bfloat16 b) {
    return (uint32_t)__bfloat16_as_ushort(a) | ((uint32_t)__bfloat16_as_ushort(b) << 16);
}

// ---------------------------------------------------------------------------
// W' = [hi | lo]  (512 bf16 per row) — for phase-1 GEMM
// ---------------------------------------------------------------------------
__global__ __launch_bounds__(256) void k_convert_w(const float* __restrict__ Wh,
                                                   const float* __restrict__ Wf) {
    int i = blockIdx.x * 256 + threadIdx.x;
    int e8 = i & 31;
    int nn = i >> 5;
    int cell = nn >> 9;
    int n = nn & 511;
    const float* W = cell ? Wf : Wh;
    const float4* src = reinterpret_cast<const float4*>(W + (size_t)n * EE + e8 * 8);
    float4 v0 = src[0], v1 = src[1];
    float x[8] = {v0.x, v0.y, v0.z, v0.w, v1.x, v1.y, v1.z, v1.w};
    __nv_bfloat16 hi[8], lo[8];
#pragma unroll
    for (int j = 0; j < 8; j++) {
        hi[j] = __float2bfloat16(x[j]);
        lo[j] = __float2bfloat16(x[j] - __bfloat162float(hi[j]));
    }
    uint4 ph, pl;
    ph.x = bfpack(hi[0], hi[1]); ph.y = bfpack(hi[2], hi[3]);
    ph.z = bfpack(hi[4], hi[5]); ph.w = bfpack(hi[6], hi[7]);
    pl.x = bfpack(lo[0], lo[1]); pl.y = bfpack(lo[2], lo[3]);
    pl.z = bfpack(lo[4], lo[5]); pl.w = bfpack(lo[6], lo[7]);
    __nv_bfloat16* dst = g_wp + (size_t)nn * WKT + e8 * 8;
    *reinterpret_cast<uint4*>(dst)       = ph;
    *reinterpret_cast<uint4*>(dst + 256) = pl;
}

// ---------------------------------------------------------------------------
// Phase 1 fused GEMM (unchanged from R9/R10 — validated)
// ---------------------------------------------------------------------------
#define OFF_B   20480
#define OFF_BIAS 102400
#define SMEM_P1 (102400 + 1024)

__global__ __launch_bounds__(256, 2) void k_mma_gemm(
    const float* __restrict__ Xh, const float* __restrict__ Xf,
    const float* __restrict__ bih_h, const float* __restrict__ bhh_h,
    const float* __restrict__ bih_f, const float* __restrict__ bhh_f)
{
    extern __shared__ __align__(16) char smem[];
    const uint32_t sbase = smem_u32(smem);
    float* bias_s = reinterpret_cast<float*>(smem + OFF_BIAS);

    const int tid  = threadIdx.x;
    const int wid  = tid >> 5;
    const int lane = tid & 31;
    const int n0 = blockIdx.x * 256;
    const int m0 = blockIdx.y * 64;
    const int cell = m0 >> 17;

    {
        const float* bi = cell ? bih_f : bih_h;
        const float* bh = cell ? bhh_f : bhh_h;
        bias_s[tid] = bi[n0 + tid] + bh[n0 + tid];
    }

    const float* X = cell ? Xf : Xh;

    const int arow = tid >> 2;
    const int aq   = (tid & 3) * 8;
    const int rA = (m0 + arow) & (MROWS - 1);
    const float* xsrc = X + (((size_t)(rA & 255)) * LL + (rA >> 8)) * EE + aq;
    const uint32_t a_sts_h = sbase + arow * 80 + aq * 2;
    const uint32_t a_sts_l = a_sts_h + 5120;

    const int warp_m = wid & 1;
    const int warp_n = wid >> 1;
    uint32_t a_off[2];
#pragma unroll
    for (int im = 0; im < 2; im++)
        a_off[im] = (warp_m * 32 + im * 16 + (lane & 15)) * 80 + (lane >> 4) * 16;
    uint32_t b_off[4];
#pragma unroll
    for (int ip = 0; ip < 4; ip++)
        b_off[ip] = (warp_n * 64 + ip * 16 + (lane >> 4) * 8 + (lane & 7)) * 80
                  + ((lane >> 3) & 1) * 16;

    float acc[2][8][4];
#pragma unroll
    for (int im = 0; im < 2; im++)
#pragma unroll
        for (int in = 0; in < 8; in++)
#pragma unroll
            for (int q = 0; q < 4; q++) acc[im][in][q] = 0.0f;

#define LOAD_B(chunk)                                                          \
    do {                                                                       \
        const int _k0 = (chunk) * 32;                                          \
        const uint32_t _bb = sbase + OFF_B + (uint32_t)((chunk) & 1) * 40960;  \
        _Pragma("unroll")                                                      \
        for (int _i = 0; _i < 8; _i++) {                                       \
            int _idx = tid + _i * 256;                                         \
            int _half = _idx >> 10;                                            \
            int _r2 = _idx & 1023;                                             \
            int _brow = _r2 >> 2;                                              \
            int _pc = _r2 & 3;                                                 \
            cp16(_bb + _half * 20480 + _brow * 80 + _pc * 16,                  \
                 g_wp + ((size_t)cell * G4 + n0 + _brow) * WKT                 \
                      + _half * 256 + _k0 + _pc * 8);                          \
        }                                                                      \
        cp_commit();                                                           \
    } while (0)

    float4 xr0 = reinterpret_cast<const float4*>(xsrc)[0];
    float4 xr1 = reinterpret_cast<const float4*>(xsrc)[1];
    LOAD_B(0);

    for (int k = 0; k < 8; ++k) {
        const uint32_t aboff = (uint32_t)(k & 1) * 10240;
        const uint32_t bboff = (uint32_t)(k & 1) * 40960;

        {
            float x8[8] = {xr0.x, xr0.y, xr0.z, xr0.w, xr1.x, xr1.y, xr1.z, xr1.w};
            __nv_bfloat16 hi[8], lo[8];
#pragma unroll
            for (int j = 0; j < 8; j++) {
                hi[j] = __float2bfloat16(x8[j]);
                lo[j] = __float2bfloat16(x8[j] - __bfloat162float(hi[j]));
            }
            uint4 ph, pl;
            ph.x = bfpack(hi[0], hi[1]); ph.y = bfpack(hi[2], hi[3]);
            ph.z = bfpack(hi[4], hi[5]); ph.w = bfpack(hi[6], hi[7]);
            pl.x = bfpack(lo[0], lo[1]); pl.y = bfpack(lo[2], lo[3]);
            pl.z = bfpack(lo[4], lo[5]); pl.w = bfpack(lo[6], lo[7]);
            asm volatile("st.shared.v4.b32 [%0], {%1,%2,%3,%4};"
                         :: "r"(a_sts_h + aboff), "r"(ph.x), "r"(ph.y), "r"(ph.z), "r"(ph.w)
                         : "memory");
            asm volatile("st.shared.v4.b32 [%0], {%1,%2,%3,%4};"
                         :: "r"(a_sts_l + aboff), "r"(pl.x), "r"(pl.y), "r"(pl.z), "r"(pl.w)
                         : "memory");
        }
        if (k < 7) {
            xr0 = reinterpret_cast<const float4*>(xsrc + (k + 1) * 32)[0];
            xr1 = reinterpret_cast<const float4*>(xsrc + (k + 1) * 32)[1];
        }
        cp_wait<0>();
        __syncthreads();
        if (k < 7) LOAD_B(k + 1);

#pragma unroll
        for (int ks = 0; ks < 2; ks++) {
            const uint32_t kb = ks * 32;
            uint32_t ahi[2][4], bfr[16];
            ldx4(ahi[0], sbase + aboff + a_off[0] + kb);
            ldx4(ahi[1], sbase + aboff + a_off[1] + kb);
#pragma unroll
            for (int ip = 0; ip < 4; ip++)
                ldx4(bfr + ip * 4, sbase + OFF_B + bboff + b_off[ip] + kb);
#pragma unroll
            for (int im = 0; im < 2; im++)
#pragma unroll
                for (int in = 0; in < 8; in++)
                    mma16816(acc[im][in], ahi[im], bfr[in * 2], bfr[in * 2 + 1]);
            {
                uint32_t alo[2][4];
                ldx4(alo[0], sbase + aboff + 5120 + a_off[0] + kb);
                ldx4(alo[1], sbase + aboff + 5120 + a_off[1] + kb);
#pragma unroll
                for (int im = 0; im < 2; im++)
#pragma unroll
                    for (int in = 0; in < 8; in++)
                        mma16816(acc[im][in], alo[im], bfr[in * 2], bfr[in * 2 + 1]);
            }
#pragma unroll
            for (int ip = 0; ip < 4; ip++)
                ldx4(bfr + ip * 4, sbase + OFF_B + bboff + 20480 + b_off[ip] + kb);
#pragma unroll
            for (int im = 0; im < 2; im++)
#pragma unroll
                for (int in = 0; in < 8; in++)
                    mma16816(acc[im][in], ahi[im], bfr[in * 2], bfr[in * 2 + 1]);
        }
    }
    __syncthreads();

#pragma unroll
    for (int im = 0; im < 2; im++) {
#pragma unroll
        for (int h = 0; h < 2; h++) {
            int m = m0 + warp_m * 32 + im * 16 + h * 8 + (lane >> 2);
            int r = m & (MROWS - 1);
            int t = r >> 8, b = r & 255;
            float* gp = g_gx + (((size_t)cell * LL + t) * BB + b) * G4 + n0;
#pragma unroll
            for (int in = 0; in < 8; in++) {
                int col = warp_n * 64 + in * 8 + (lane & 3) * 2;
                float2 v;
                v.x = acc[im][in][2 * h + 0] + bias_s[col];
                v.y = acc[im][in][2 * h + 1] + bias_s[col + 1];
                *reinterpret_cast<float2*>(gp + col) = v;
            }
        }
    }
}

// ---------------------------------------------------------------------------
// Phase 2: recurrent LSTM v3 — R6/R10 skeleton (cluster 4, 256 thr, 2/SM,
// DSMEM broadcast, 1 syncthreads + 1 cluster barrier), matvec on TENSOR pipe:
// gates = W.h via mma.sync m16n8k16 bf16 hi/lo split.
//   - W fragments resident in regs (warp w owns rows w*16..+15; 8 ktiles x
//     4 regs x {hi,lo} = 64 regs)
//   - h in smem as bf16x2 (k,k+1) pairs, hi+lo arrays, stride 68 u32
//     (B-frag LDS.32: bank = 4*gid+tig — conflict-free)
//   - pointwise converts hv -> hi/lo bf16, u16 stores local + 3 remote peers
// ---------------------------------------------------------------------------
__global__ __launch_bounds__(256, 2) __cluster_dims__(4, 1, 1)
void k_recurrent(const float* __restrict__ Whh_h,
                 const float* __restrict__ Whh_f)
{
    __shared__ uint32_t hp_hi[2][TB][68];    // [buf][batch][k-pair] bf16x2
    __shared__ uint32_t hp_lo[2][TB][68];
    __shared__ float gates_s[128][10];

    const int tid = threadIdx.x;
    uint32_t rank;
    asm("mov.u32 %0, %%cluster_ctarank;" : "=r"(rank));
    const int q    = blockIdx.x >> 2;
    const int cell = q >> 5;
    const int b0   = (q & 31) * TB;

    const float* W = cell ? Whh_f : Whh_h;

    const int w    = tid >> 5;
    const int lane = tid & 31;
    const int gid  = lane >> 2;             // 0..7
    const int tig  = lane & 3;              // 0..3

    // warp rows (local gate rows): rloc0 = w*16+gid, rloc1 = rloc0+8
    const int rloc0 = w * 16 + gid;
    const int rloc1 = rloc0 + 8;
    const int ng0 = (rloc0 >> 5) * HH + (int)rank * 32 + (rloc0 & 31);
    const int ng1 = (rloc1 >> 5) * HH + (int)rank * 32 + (rloc1 & 31);

    // A fragments: W rows ng0/ng1, hi+lo, 8 ktiles
    uint32_t a_hi[8][4], a_lo[8][4];
#pragma unroll
    for (int kt = 0; kt < 8; kt++) {
        int c0 = kt * 16 + 2 * tig;
#pragma unroll
        for (int rr = 0; rr < 2; rr++) {
            const float* wr = W + (size_t)(rr ? ng1 : ng0) * HH;
#pragma unroll
            for (int cc = 0; cc < 2; cc++) {       // cc=0 -> c0, cc=1 -> c0+8
                float xa = wr[c0 + cc * 8];
                float xb = wr[c0 + cc * 8 + 1];
                __nv_bfloat16 ha = __float2bfloat16(xa);
                __nv_bfloat16 hb = __float2bfloat16(xb);
                __nv_bfloat16 la = __float2bfloat16(xa - __bfloat162float(ha));
                __nv_bfloat16 lb = __float2bfloat16(xb - __bfloat162float(hb));
                a_hi[kt][cc * 2 + rr] = bfpack(ha, hb);
                a_lo[kt][cc * 2 + rr] = bfpack(la, lb);
            }
        }
    }

    // pointwise mapping (warp = batch)
    const int pb = tid >> 5;
    const int pj = tid & 31;
    const int jglob = (int)rank * 32 + pj;
    // u16 offsets into hp arrays: [pb][*] flat u16 index = pb*136 + jglob
    const uint32_t hhi_u16_0 = smem_u32(&hp_hi[0][0][0]) + (pb * 136 + jglob) * 2;
    const uint32_t hhi_u16_1 = smem_u32(&hp_hi[1][0][0]) + (pb * 136 + jglob) * 2;
    const uint32_t hlo_u16_0 = smem_u32(&hp_lo[0][0][0]) + (pb * 136 + jglob) * 2;
    const uint32_t hlo_u16_1 = smem_u32(&hp_lo[1][0][0]) + (pb * 136 + jglob) * 2;
    float* hg = g_h + (((size_t)cell * BB + b0 + pb) * LL) * HH + jglob;

    for (int i = tid; i < 2 * TB * 68; i += 256) {
        (&hp_hi[0][0][0])[i] = 0u;
        (&hp_lo[0][0][0])[i] = 0u;
    }
    float c_reg = 0.0f;
    __syncthreads();
    asm volatile("barrier.cluster.arrive.aligned;" ::: "memory");
    asm volatile("barrier.cluster.wait.aligned;"   ::: "memory");

    const float* gxbase = g_gx + ((size_t)cell * LL * BB + (b0 + pb)) * G4 + jglob;
    float gxr[4];
#pragma unroll
    for (int gi = 0; gi < 4; gi++)
        gxr[gi] = gxbase[gi * HH];

    const uint32_t* hhi_base = &hp_hi[0][0][0];
    const uint32_t* hlo_base = &hp_lo[0][0][0];

    int buf = 0;
    for (int t = 0; t < LL; t++) {
        // ---- gates via tensor pipe: c[4] = W . h  (3-product hi/lo)
        float cfr[4] = {0.0f, 0.0f, 0.0f, 0.0f};
        const int fb = buf * TB * 68 + gid * 68;
#pragma unroll
        for (int kt = 0; kt < 8; kt++) {
            int pidx = fb + kt * 8 + tig;
            uint32_t bh0 = hhi_base[pidx];
            uint32_t bh1 = hhi_base[pidx + 4];
            uint32_t bl0 = hlo_base[pidx];
            uint32_t bl1 = hlo_base[pidx + 4];
            mma16816(cfr, a_hi[kt], bh0, bh1);
            mma16816(cfr, a_hi[kt], bl0, bl1);
            mma16816(cfr, a_lo[kt], bh0, bh1);
        }
        // store gates: rows rloc0/rloc1, cols (batches) 2tig, 2tig+1
        *reinterpret_cast<float2*>(&gates_s[rloc0][2 * tig]) =
            make_float2(cfr[0], cfr[1]);
        *reinterpret_cast<float2*>(&gates_s[rloc1][2 * tig]) =
            make_float2(cfr[2], cfr[3]);
        __syncthreads();

        // ---- pointwise: unit (pb, jglob)
        float gi_ = gates_s[pj][pb]       + gxr[0];
        float gf_ = gates_s[32 + pj][pb]  + gxr[1];
        float gg_ = gates_s[64 + pj][pb]  + gxr[2];
        float go_ = gates_s[96 + pj][pb]  + gxr[3];
        float ig = sigm(gi_);
        float fg = sigm(gf_);
        float gv = tanha(gg_);
        float og = sigm(go_);
        c_reg = fg * c_reg + ig * gv;
        float hv = og * tanha(c_reg);

        __nv_bfloat16 hhi = __float2bfloat16(hv);
        __nv_bfloat16 hlo = __float2bfloat16(hv - __bfloat162float(hhi));
        uint16_t hhi_b = __bfloat16_as_ushort(hhi);
        uint16_t hlo_b = __bfloat16_as_ushort(hlo);

        const int nb = buf ^ 1;
        const uint32_t ahh = nb ? hhi_u16_1 : hhi_u16_0;
        const uint32_t ahl = nb ? hlo_u16_1 : hlo_u16_0;
        asm volatile("st.shared.b16 [%0], %1;" :: "r"(ahh), "h"(hhi_b) : "memory");
        asm volatile("st.shared.b16 [%0], %1;" :: "r"(ahl), "h"(hlo_b) : "memory");
#pragma unroll
        for (int r = 1; r < 4; r++) {
            st_remote_b16(ahh, (rank + r) & 3u, hhi_b);
            st_remote_b16(ahl, (rank + r) & 3u, hlo_b);
        }
        hg[(size_t)t * HH] = hv;

        if (t + 1 < LL) {
            const float* gp = gxbase + (size_t)(t + 1) * BB * G4;
#pragma unroll
            for (int gi2 = 0; gi2 < 4; gi2++)
                gxr[gi2] = gp[gi2 * HH];
        }

        asm volatile("barrier.cluster.arrive.aligned;" ::: "memory");
        asm volatile("barrier.cluster.wait.aligned;"   ::: "memory");
        buf = nb;
    }
}

// ---------------------------------------------------------------------------
// Phase 3: y[b][t] = W_ffn . [h_h(b,t); h_f(b,t)] + b_ffn  (R9 version)
// ---------------------------------------------------------------------------
__global__ __launch_bounds__(256) void k_finalize(float* __restrict__ out,
                                                  const float* __restrict__ Wffn,
                                                  const float* __restrict__ bffn) {
    __shared__ float wf[2 * HH];
    const int b = blockIdx.x >> 1;
    const int t = (blockIdx.x & 1) * 256 + threadIdx.x;
    wf[threadIdx.x] = Wffn[threadIdx.x];
    __syncthreads();
    const float bias = bffn[0];

    const float4* p0 = reinterpret_cast<const float4*>(
        g_h + (((size_t)0 * BB + b) * LL + t) * HH);
    const float4* p1 = reinterpret_cast<const float4*>(
        g_h + (((size_t)1 * BB + b) * LL + t) * HH);
    float acc = bias;
#pragma unroll 8
    for (int q = 0; q < 32; q++) {
        float4 a = p0[q];
        acc += a.x * wf[4 * q] + a.y * wf[4 * q + 1]
             + a.z * wf[4 * q + 2] + a.w * wf[4 * q + 3];
    }
#pragma unroll 8
    for (int q = 0; q < 32; q++) {
        float4 a = p1[q];
        acc += a.x * wf[128 + 4 * q] + a.y * wf[128 + 4 * q + 1]
             + a.z * wf[128 + 4 * q + 2] + a.w * wf[128 + 4 * q + 3];
    }
    out[(size_t)b * LL + t] = acc;
}

// ---------------------------------------------------------------------------
extern "C" void kernel_launch(void* const* d_in, const int* in_sizes, int n_in,
                              void* d_out, int out_size) {
    const float* hist  = (const float*)d_in[0];
    const float* fut   = (const float*)d_in[1];
    const float* Wih_h = (const float*)d_in[2];
    const float* Whh_h = (const float*)d_in[3];
    const float* bih_h = (const float*)d_in[4];
    const float* bhh_h = (const float*)d_in[5];
    const float* Wih_f = (const float*)d_in[6];
    const float* Whh_f = (const float*)d_in[7];
    const float* bih_f = (const float*)d_in[8];
    const float* bhh_f = (const float*)d_in[9];
    const float* Wffn  = (const float*)d_in[10];
    const float* bffn  = (const float*)d_in[11];
    float* out = (float*)d_out;

    static int smem_set = 0;
    if (!smem_set) {
        cudaFuncSetAttribute(k_mma_gemm,
                             cudaFuncAttributeMaxDynamicSharedMemorySize, SMEM_P1);
        smem_set = 1;
    }

    k_convert_w<<<(2 * G4 * 32) / 256, 256>>>(Wih_h, Wih_f);

    dim3 gg(G4 / 256, (2 * MROWS) / 64);   // (2, 4096)
    k_mma_gemm<<<gg, 256, SMEM_P1>>>(hist, fut, bih_h, bhh_h, bih_f, bhh_f);

    k_recurrent<<<256, 256>>>(Whh_h, Whh_f);

    k_finalize<<<2 * BB, 256>>>(out, Wffn, bffn);
}